// round 2
// baseline (speedup 1.0000x reference)
#include <cuda_runtime.h>
#include <cstddef>

// Problem constants
#define L_  6
#define H_  8
#define M_  1024
#define K_  128
#define V_  128
#define F_  4096
#define B_  4
#define Q_  1024
#define T_  1024
#define BQ_ 4096   // B_*Q_

// ---------------------------------------------------------------------------
// Scratch (device globals; no runtime allocation allowed)
// ---------------------------------------------------------------------------
__device__ float g_swq[(size_t)L_ * M_ * H_ * K_];   // transposed: [l][m][h*K+d]
__device__ float g_swk[(size_t)L_ * M_ * H_ * K_];
__device__ float g_swv[(size_t)L_ * M_ * H_ * V_];
__device__ float g_cwq[(size_t)L_ * M_ * H_ * K_];
__device__ float g_cwk[(size_t)L_ * M_ * H_ * K_];
__device__ float g_cwv[(size_t)L_ * M_ * H_ * V_];

__device__ float g_h  [(size_t)BQ_ * M_];
__device__ float g_n  [(size_t)BQ_ * M_];
__device__ float g_q  [(size_t)BQ_ * M_];
__device__ float g_k  [(size_t)BQ_ * M_];
__device__ float g_v  [(size_t)BQ_ * M_];
__device__ float g_pre[(size_t)BQ_ * M_];
__device__ float g_att[(size_t)B_ * H_ * Q_ * T_];   // 134 MB
__device__ float g_s  [(size_t)BQ_ * F_];            // 67 MB

// ---------------------------------------------------------------------------
// Block reductions (blockDim.x == 256)
// ---------------------------------------------------------------------------
__device__ __forceinline__ float block_sum(float v) {
    __shared__ float sh[8];
    #pragma unroll
    for (int o = 16; o > 0; o >>= 1) v += __shfl_xor_sync(0xffffffffu, v, o);
    __syncthreads();
    if ((threadIdx.x & 31) == 0) sh[threadIdx.x >> 5] = v;
    __syncthreads();
    float t = 0.f;
    #pragma unroll
    for (int i = 0; i < 8; ++i) t += sh[i];
    return t;
}

__device__ __forceinline__ float block_max(float v) {
    __shared__ float sh[8];
    #pragma unroll
    for (int o = 16; o > 0; o >>= 1) v = fmaxf(v, __shfl_xor_sync(0xffffffffu, v, o));
    __syncthreads();
    if ((threadIdx.x & 31) == 0) sh[threadIdx.x >> 5] = v;
    __syncthreads();
    float t = sh[0];
    #pragma unroll
    for (int i = 1; i < 8; ++i) t = fmaxf(t, sh[i]);
    return t;
}

// ---------------------------------------------------------------------------
// Weight transpose: (L,H,M,K) -> (L,M,H*K)   [one element per thread]
// total = L*H*M*K = 6291456, grid 24576 x 256
// ---------------------------------------------------------------------------
__global__ void __launch_bounds__(256)
transpose_w_k(const float* __restrict__ src, float* __restrict__ dst)
{
    int idx = blockIdx.x * 256 + threadIdx.x;
    int d = idx & 127;
    int m = (idx >> 7) & 1023;
    int h = (idx >> 17) & 7;
    int l = idx >> 20;
    dst[((size_t)(l * M_ + m) << 10) + (h << 7) + d] = src[idx];
}

// ---------------------------------------------------------------------------
// LayerNorm over last dim (M=1024). One block (256 thr) per row.
// ---------------------------------------------------------------------------
__global__ void __launch_bounds__(256)
layernorm_k(const float* __restrict__ x, const float* __restrict__ g,
            const float* __restrict__ b, float* __restrict__ out)
{
    const int row = blockIdx.x;
    const float* xp = x + (size_t)row * M_;
    const int c = threadIdx.x << 2;
    float4 d = *(const float4*)(xp + c);
    float s  = d.x + d.y + d.z + d.w;
    float ss = d.x * d.x + d.y * d.y + d.z * d.z + d.w * d.w;
    s  = block_sum(s);
    ss = block_sum(ss);
    const float mean = s * (1.f / M_);
    const float var  = ss * (1.f / M_) - mean * mean;
    const float inv  = rsqrtf(var + 1e-5f);
    float4 g4 = *(const float4*)(g + c);
    float4 b4 = *(const float4*)(b + c);
    float4 o;
    o.x = (d.x - mean) * inv * g4.x + b4.x;
    o.y = (d.y - mean) * inv * g4.y + b4.y;
    o.z = (d.z - mean) * inv * g4.z + b4.z;
    o.w = (d.w - mean) * inv * g4.w + b4.w;
    *(float4*)(out + (size_t)row * M_ + c) = o;
}

// ---------------------------------------------------------------------------
// Masked softmax over T=1024. One block (256 thr) per attention row.
// row = b*H*Q + h*Q + q.  v = (logit - mask*1e6) * (1/sqrt(128))
// ---------------------------------------------------------------------------
__global__ void __launch_bounds__(256)
attn_softmax_k(float* __restrict__ att, const float* __restrict__ tmask,
               const float* __restrict__ qtmask)
{
    const int row = blockIdx.x;
    const int b = row >> 13;          // H*Q = 8192
    const int q = row & (Q_ - 1);
    float* p = att + (size_t)row * T_;
    const float inv = 0.08838834764831845f;   // 1/sqrt(128)
    float vals[4];
    float mx = -3.0e38f;
    #pragma unroll
    for (int i = 0; i < 4; ++i) {
        int t = threadIdx.x + (i << 8);
        float m = tmask ? tmask[b * T_ + t] : 0.f;
        if (qtmask) m = fmaxf(m, qtmask[((size_t)(b * Q_ + q)) * T_ + t]);
        float v = (p[t] - m * 1e6f) * inv;
        vals[i] = v;
        mx = fmaxf(mx, v);
    }
    mx = block_max(mx);
    float s = 0.f;
    #pragma unroll
    for (int i = 0; i < 4; ++i) { vals[i] = expf(vals[i] - mx); s += vals[i]; }
    s = block_sum(s);
    const float r = 1.f / s;
    #pragma unroll
    for (int i = 0; i < 4; ++i) p[threadIdx.x + (i << 8)] = vals[i] * r;
}

// ---------------------------------------------------------------------------
// Generic SGEMM: C = A * B (optionally B transposed: B is N x K row-major).
// 128x128 block tile, BK=8, 256 threads, 8x8 per-thread, smem double-buffer
// with register prefetch. All dims assumed multiples of tile sizes (they are).
// Batch via blockIdx.z with (b,h)=(z>>3, z&7) two-level strides.
// EPI: 0 C=acc | 1 C=resid+acc*(1-mask[r]) | 2 C=relu(acc+bias[n])
//      3 C=resid+(acc+bias[n])*(1-mask[r])
// ---------------------------------------------------------------------------
template <bool TRANSB, int EPI>
__global__ void __launch_bounds__(256)
gemm_k(const float* __restrict__ A, int lda, long long sAb, long long sAh,
       const float* __restrict__ Bm, int ldb, long long sBb, long long sBh,
       float* __restrict__ C, int ldc, long long sCb, long long sCh,
       const float* __restrict__ resid, int ldr,
       const float* __restrict__ bias,
       const float* __restrict__ rowmask,
       int Kdim)
{
    const int z = blockIdx.z;
    A  += (long long)(z >> 3) * sAb + (long long)(z & 7) * sAh;
    Bm += (long long)(z >> 3) * sBb + (long long)(z & 7) * sBh;
    C  += (long long)(z >> 3) * sCb + (long long)(z & 7) * sCh;

    __shared__ __align__(16) float As[2][8][128];
    __shared__ __align__(16) float Bs[2][8][128];

    const int tid  = threadIdx.x;
    const int rowg = tid >> 4;          // 0..15
    const int colg = tid & 15;          // 0..15
    const int m0 = blockIdx.y << 7;
    const int n0 = blockIdx.x << 7;

    const int la_r = tid >> 1;          // 0..127
    const int la_k = (tid & 1) << 2;    // 0 or 4
    const int lb_k = tid >> 5;          // 0..7
    const int lb_n = (tid & 31) << 2;   // 0..124

    const float* Aload = A + (long long)(m0 + la_r) * lda + la_k;
    const float* Bload = TRANSB ? (Bm + (long long)(n0 + la_r) * ldb + la_k)
                                : (Bm + (long long)lb_k * ldb + n0 + lb_n);

    float acc[8][8];
    #pragma unroll
    for (int i = 0; i < 8; ++i)
        #pragma unroll
        for (int j = 0; j < 8; ++j) acc[i][j] = 0.f;

    const int ntiles = Kdim >> 3;

    // prologue: tile 0 -> stage 0
    {
        float4 aR = *(const float4*)(Aload);
        float4 bR = *(const float4*)(Bload);
        As[0][la_k + 0][la_r] = aR.x;
        As[0][la_k + 1][la_r] = aR.y;
        As[0][la_k + 2][la_r] = aR.z;
        As[0][la_k + 3][la_r] = aR.w;
        if (TRANSB) {
            Bs[0][la_k + 0][la_r] = bR.x;
            Bs[0][la_k + 1][la_r] = bR.y;
            Bs[0][la_k + 2][la_r] = bR.z;
            Bs[0][la_k + 3][la_r] = bR.w;
        } else {
            *(float4*)&Bs[0][lb_k][lb_n] = bR;
        }
    }
    __syncthreads();

    int st = 0;
    for (int kt = 0; kt < ntiles; ++kt) {
        float4 aN, bN;
        const bool more = (kt + 1) < ntiles;
        if (more) {
            aN = *(const float4*)(Aload + (kt + 1) * 8);
            bN = TRANSB ? *(const float4*)(Bload + (kt + 1) * 8)
                        : *(const float4*)(Bload + (long long)(kt + 1) * 8 * ldb);
        }
        #pragma unroll
        for (int kk = 0; kk < 8; ++kk) {
            float a[8], b[8];
            *(float4*)&a[0] = *(const float4*)&As[st][kk][rowg << 3];
            *(float4*)&a[4] = *(const float4*)&As[st][kk][(rowg << 3) + 4];
            *(float4*)&b[0] = *(const float4*)&Bs[st][kk][colg << 3];
            *(float4*)&b[4] = *(const float4*)&Bs[st][kk][(colg << 3) + 4];
            #pragma unroll
            for (int i = 0; i < 8; ++i)
                #pragma unroll
                for (int j = 0; j < 8; ++j)
                    acc[i][j] = fmaf(a[i], b[j], acc[i][j]);
        }
        if (more) {
            const int ns = st ^ 1;
            As[ns][la_k + 0][la_r] = aN.x;
            As[ns][la_k + 1][la_r] = aN.y;
            As[ns][la_k + 2][la_r] = aN.z;
            As[ns][la_k + 3][la_r] = aN.w;
            if (TRANSB) {
                Bs[ns][la_k + 0][la_r] = bN.x;
                Bs[ns][la_k + 1][la_r] = bN.y;
                Bs[ns][la_k + 2][la_r] = bN.z;
                Bs[ns][la_k + 3][la_r] = bN.w;
            } else {
                *(float4*)&Bs[ns][lb_k][lb_n] = bN;
            }
            __syncthreads();
            st = ns;
        }
    }

    // epilogue
    const int crow = m0 + (rowg << 3);
    const int ccol = n0 + (colg << 3);
    #pragma unroll
    for (int i = 0; i < 8; ++i) {
        const int r = crow + i;
        float mfac = 1.f;
        if (EPI == 1 || EPI == 3) mfac = 1.f - rowmask[r];
        float* cp = C + (long long)r * ldc + ccol;
        const float* rp = (EPI == 1 || EPI == 3) ? (resid + (long long)r * ldr + ccol) : nullptr;
        #pragma unroll
        for (int j = 0; j < 8; ++j) {
            float v = acc[i][j];
            if (EPI >= 2) v += bias[ccol + j];
            if (EPI == 2) v = fmaxf(v, 0.f);
            if (EPI == 1 || EPI == 3) v = rp[j] + v * mfac;
            cp[j] = v;
        }
    }
}

// ---------------------------------------------------------------------------
// Host orchestration
// ---------------------------------------------------------------------------
extern "C" void kernel_launch(void* const* d_in, const int* in_sizes, int n_in,
                              void* d_out, int out_size)
{
    (void)in_sizes; (void)n_in; (void)out_size;

    const float* enc_out = (const float*)d_in[0];
    const float* x       = (const float*)d_in[1];
    const float* pmask   = (const float*)d_in[2];
    const float* qtself  = (const float*)d_in[3];
    const float* qtcross = (const float*)d_in[4];
    const float* swq = (const float*)d_in[5];
    const float* swk = (const float*)d_in[6];
    const float* swv = (const float*)d_in[7];
    const float* swo = (const float*)d_in[8];
    const float* cwq = (const float*)d_in[9];
    const float* cwk = (const float*)d_in[10];
    const float* cwv = (const float*)d_in[11];
    const float* cwo = (const float*)d_in[12];
    const float* w1  = (const float*)d_in[13];
    const float* b1  = (const float*)d_in[14];
    const float* w2  = (const float*)d_in[15];
    const float* b2  = (const float*)d_in[16];
    const float* ln1g = (const float*)d_in[17];
    const float* ln1b = (const float*)d_in[18];
    const float* ln2g = (const float*)d_in[19];
    const float* ln2b = (const float*)d_in[20];
    const float* ln3g = (const float*)d_in[21];
    const float* ln3b = (const float*)d_in[22];

    float *wq_s, *wk_s, *wv_s, *wq_c, *wk_c, *wv_c;
    float *hb, *nb, *qb, *kb, *vb, *pb, *ab, *sb;
    cudaGetSymbolAddress((void**)&wq_s, g_swq);
    cudaGetSymbolAddress((void**)&wk_s, g_swk);
    cudaGetSymbolAddress((void**)&wv_s, g_swv);
    cudaGetSymbolAddress((void**)&wq_c, g_cwq);
    cudaGetSymbolAddress((void**)&wk_c, g_cwk);
    cudaGetSymbolAddress((void**)&wv_c, g_cwv);
    cudaGetSymbolAddress((void**)&hb, g_h);
    cudaGetSymbolAddress((void**)&nb, g_n);
    cudaGetSymbolAddress((void**)&qb, g_q);
    cudaGetSymbolAddress((void**)&kb, g_k);
    cudaGetSymbolAddress((void**)&vb, g_v);
    cudaGetSymbolAddress((void**)&pb, g_pre);
    cudaGetSymbolAddress((void**)&ab, g_att);
    cudaGetSymbolAddress((void**)&sb, g_s);

    // Weight transposes (qkv weights -> [l][m][h*K+d])
    const int tpGrid = (L_ * H_ * M_ * K_) / 256;   // 24576
    transpose_w_k<<<tpGrid, 256>>>(swq, wq_s);
    transpose_w_k<<<tpGrid, 256>>>(swk, wk_s);
    transpose_w_k<<<tpGrid, 256>>>(swv, wv_s);
    transpose_w_k<<<tpGrid, 256>>>(cwq, wq_c);
    transpose_w_k<<<tpGrid, 256>>>(cwk, wk_c);
    transpose_w_k<<<tpGrid, 256>>>(cwv, wv_c);

    // h = x
    cudaMemcpyAsync(hb, x, (size_t)BQ_ * M_ * sizeof(float),
                    cudaMemcpyDeviceToDevice);

    const dim3 gProj(M_ / 128, BQ_ / 128, 1);        // (8,32)  4096x1024
    const dim3 gQK(T_ / 128, Q_ / 128, B_ * H_);     // (8,8,32) batched
    const dim3 gAV(V_ / 128, Q_ / 128, B_ * H_);     // (1,8,32)
    const dim3 gF1(F_ / 128, BQ_ / 128, 1);          // (32,32)
    const dim3 gF2(M_ / 128, BQ_ / 128, 1);          // (8,32)

    const long long sQb = (long long)Q_ * M_;        // b-stride in q/k/v/pre
    const long long sAttB = (long long)H_ * Q_ * T_;
    const long long sAttH = (long long)Q_ * T_;

    for (int l = 0; l < L_; ++l) {
        const size_t wOff  = (size_t)l * M_ * H_ * K_;   // transposed qkv / wo
        const float* swo_l = swo + (size_t)l * H_ * V_ * M_;
        const float* cwo_l = cwo + (size_t)l * H_ * V_ * M_;

        // ---- self-attention ----
        layernorm_k<<<BQ_, 256>>>(hb, ln1g + l * M_, ln1b + l * M_, nb);
        gemm_k<false, 0><<<gProj, 256>>>(nb, M_, 0, 0, wq_s + wOff, M_, 0, 0,
                                         qb, M_, 0, 0, nullptr, 0, nullptr, nullptr, M_);
        gemm_k<false, 0><<<gProj, 256>>>(nb, M_, 0, 0, wk_s + wOff, M_, 0, 0,
                                         kb, M_, 0, 0, nullptr, 0, nullptr, nullptr, M_);
        gemm_k<false, 0><<<gProj, 256>>>(nb, M_, 0, 0, wv_s + wOff, M_, 0, 0,
                                         vb, M_, 0, 0, nullptr, 0, nullptr, nullptr, M_);
        gemm_k<true, 0><<<gQK, 256>>>(qb, M_, sQb, 128,
                                      kb, M_, sQb, 128,
                                      ab, T_, sAttB, sAttH,
                                      nullptr, 0, nullptr, nullptr, K_);
        attn_softmax_k<<<B_ * H_ * Q_, 256>>>(ab, pmask, qtself);
        gemm_k<false, 0><<<gAV, 256>>>(ab, T_, sAttB, sAttH,
                                       vb, M_, sQb, 128,
                                       pb, M_, sQb, 128,
                                       nullptr, 0, nullptr, nullptr, T_);
        gemm_k<false, 1><<<gProj, 256>>>(pb, M_, 0, 0, swo_l, M_, 0, 0,
                                         hb, M_, 0, 0, hb, M_, nullptr, pmask, H_ * V_);

        // ---- cross-attention ----
        layernorm_k<<<BQ_, 256>>>(hb, ln2g + l * M_, ln2b + l * M_, nb);
        gemm_k<false, 0><<<gProj, 256>>>(nb, M_, 0, 0, wq_c + wOff, M_, 0, 0,
                                         qb, M_, 0, 0, nullptr, 0, nullptr, nullptr, M_);
        gemm_k<false, 0><<<gProj, 256>>>(enc_out, M_, 0, 0, wk_c + wOff, M_, 0, 0,
                                         kb, M_, 0, 0, nullptr, 0, nullptr, nullptr, M_);
        gemm_k<false, 0><<<gProj, 256>>>(enc_out, M_, 0, 0, wv_c + wOff, M_, 0, 0,
                                         vb, M_, 0, 0, nullptr, 0, nullptr, nullptr, M_);
        gemm_k<true, 0><<<gQK, 256>>>(qb, M_, sQb, 128,
                                      kb, M_, sQb, 128,
                                      ab, T_, sAttB, sAttH,
                                      nullptr, 0, nullptr, nullptr, K_);
        attn_softmax_k<<<B_ * H_ * Q_, 256>>>(ab, nullptr, qtcross);
        gemm_k<false, 0><<<gAV, 256>>>(ab, T_, sAttB, sAttH,
                                       vb, M_, sQb, 128,
                                       pb, M_, sQb, 128,
                                       nullptr, 0, nullptr, nullptr, T_);
        gemm_k<false, 1><<<gProj, 256>>>(pb, M_, 0, 0, cwo_l, M_, 0, 0,
                                         hb, M_, 0, 0, hb, M_, nullptr, pmask, H_ * V_);

        // ---- FFN ----
        layernorm_k<<<BQ_, 256>>>(hb, ln3g + l * M_, ln3b + l * M_, nb);
        gemm_k<false, 2><<<gF1, 256>>>(nb, M_, 0, 0, w1 + (size_t)l * M_ * F_, F_, 0, 0,
                                       sb, F_, 0, 0, nullptr, 0, b1 + l * F_, nullptr, M_);
        gemm_k<false, 3><<<gF2, 256>>>(sb, F_, 0, 0, w2 + (size_t)l * F_ * M_, M_, 0, 0,
                                       hb, M_, 0, 0, hb, M_, b2 + l * M_, pmask, F_);
    }

    cudaMemcpyAsync(d_out, hb, (size_t)BQ_ * M_ * sizeof(float),
                    cudaMemcpyDeviceToDevice);
}

// round 4
// speedup vs baseline: 2.3456x; 2.3456x over previous
#include <cuda_runtime.h>
#include <cuda_bf16.h>
#include <cstdint>
#include <cstddef>

// Problem constants
#define L_  6
#define H_  8
#define M_  1024
#define K_  128
#define V_  128
#define F_  4096
#define B_  4
#define Q_  1024
#define T_  1024
#define BQ_ 4096   // B_*Q_

// ===========================================================================
// Low-level helpers (base PTX only — no sm_103a-specific instructions)
// ===========================================================================
__device__ __forceinline__ uint32_t smem_to_u32(const void* p) {
    uint32_t a;
    asm("{ .reg .u64 t; cvta.to.shared.u64 t, %1; cvt.u32.u64 %0, t; }"
        : "=r"(a) : "l"(p));
    return a;
}

__device__ __forceinline__ void cp16(uint32_t dst, const void* src) {
    asm volatile("cp.async.cg.shared.global [%0], [%1], 16;"
                 :: "r"(dst), "l"(__cvta_generic_to_global(src)));
}
__device__ __forceinline__ void cp_commit() { asm volatile("cp.async.commit_group;" ::: "memory"); }
__device__ __forceinline__ void cp_wait0()  { asm volatile("cp.async.wait_group 0;" ::: "memory"); }
__device__ __forceinline__ void cp_wait1()  { asm volatile("cp.async.wait_group 1;" ::: "memory"); }

__device__ __forceinline__ void ldsm_x4(uint32_t* r, uint32_t addr) {
    asm volatile("ldmatrix.sync.aligned.m8n8.x4.shared.b16 {%0,%1,%2,%3}, [%4];"
                 : "=r"(r[0]), "=r"(r[1]), "=r"(r[2]), "=r"(r[3]) : "r"(addr));
}

__device__ __forceinline__ void mma16816(float* d, const uint32_t* a, const uint32_t* b) {
    asm volatile(
        "mma.sync.aligned.m16n8k16.row.col.f32.bf16.bf16.f32 "
        "{%0,%1,%2,%3}, {%4,%5,%6,%7}, {%8,%9}, {%0,%1,%2,%3};"
        : "+f"(d[0]), "+f"(d[1]), "+f"(d[2]), "+f"(d[3])
        : "r"(a[0]), "r"(a[1]), "r"(a[2]), "r"(a[3]), "r"(b[0]), "r"(b[1]));
}

// ===========================================================================
// Scratch (device globals; no runtime allocation allowed)
// ===========================================================================
__device__ float g_h  [(size_t)BQ_ * M_];
__device__ float g_att[(size_t)B_ * H_ * Q_ * T_];   // 134 MB fp32 logits

// bf16 split weights: [N][K] k-major, per layer contiguous
#define WQKV_SZ ((size_t)L_ * 1048576)   // L * (H*128) * M
#define WFF_SZ  ((size_t)L_ * 4194304)   // L * F * M
__device__ __align__(256) __nv_bfloat16 g_wqs_h[WQKV_SZ], g_wqs_l[WQKV_SZ];
__device__ __align__(256) __nv_bfloat16 g_wks_h[WQKV_SZ], g_wks_l[WQKV_SZ];
__device__ __align__(256) __nv_bfloat16 g_wvs_h[WQKV_SZ], g_wvs_l[WQKV_SZ];
__device__ __align__(256) __nv_bfloat16 g_wqc_h[WQKV_SZ], g_wqc_l[WQKV_SZ];
__device__ __align__(256) __nv_bfloat16 g_wkc_h[WQKV_SZ], g_wkc_l[WQKV_SZ];
__device__ __align__(256) __nv_bfloat16 g_wvc_h[WQKV_SZ], g_wvc_l[WQKV_SZ];
__device__ __align__(256) __nv_bfloat16 g_wos_h[WQKV_SZ], g_wos_l[WQKV_SZ];
__device__ __align__(256) __nv_bfloat16 g_woc_h[WQKV_SZ], g_woc_l[WQKV_SZ];
__device__ __align__(256) __nv_bfloat16 g_w1_h[WFF_SZ],  g_w1_l[WFF_SZ];
__device__ __align__(256) __nv_bfloat16 g_w2_h[WFF_SZ],  g_w2_l[WFF_SZ];

// bf16 split activations
__device__ __align__(256) __nv_bfloat16 g_nh [(size_t)BQ_ * M_], g_nl [(size_t)BQ_ * M_];
__device__ __align__(256) __nv_bfloat16 g_qh [(size_t)BQ_ * M_], g_ql [(size_t)BQ_ * M_];
__device__ __align__(256) __nv_bfloat16 g_kh [(size_t)BQ_ * M_], g_kl [(size_t)BQ_ * M_];
__device__ __align__(256) __nv_bfloat16 g_vth[(size_t)M_ * BQ_], g_vtl[(size_t)M_ * BQ_];
__device__ __align__(256) __nv_bfloat16 g_ph [(size_t)BQ_ * M_], g_pl [(size_t)BQ_ * M_];
__device__ __align__(256) __nv_bfloat16 g_eh [(size_t)B_ * T_ * M_], g_el [(size_t)B_ * T_ * M_];
__device__ __align__(256) __nv_bfloat16 g_sh [(size_t)BQ_ * F_], g_sl [(size_t)BQ_ * F_];
__device__ __align__(256) __nv_bfloat16 g_ath[(size_t)B_ * H_ * Q_ * T_], g_atl[(size_t)B_ * H_ * Q_ * T_];

// ===========================================================================
// Block reductions (blockDim.x == 256)
// ===========================================================================
__device__ __forceinline__ float block_sum(float v) {
    __shared__ float sh[8];
    #pragma unroll
    for (int o = 16; o > 0; o >>= 1) v += __shfl_xor_sync(0xffffffffu, v, o);
    __syncthreads();
    if ((threadIdx.x & 31) == 0) sh[threadIdx.x >> 5] = v;
    __syncthreads();
    float t = 0.f;
    #pragma unroll
    for (int i = 0; i < 8; ++i) t += sh[i];
    return t;
}

__device__ __forceinline__ float block_max(float v) {
    __shared__ float sh[8];
    #pragma unroll
    for (int o = 16; o > 0; o >>= 1) v = fmaxf(v, __shfl_xor_sync(0xffffffffu, v, o));
    __syncthreads();
    if ((threadIdx.x & 31) == 0) sh[threadIdx.x >> 5] = v;
    __syncthreads();
    float t = sh[0];
    #pragma unroll
    for (int i = 1; i < 8; ++i) t = fmaxf(t, sh[i]);
    return t;
}

// ===========================================================================
// Batched transpose + bf16 hi/lo split: [batch][R][C] fp32 -> [batch][C][R]
// ===========================================================================
__global__ void __launch_bounds__(256)
tsplit_k(const float* __restrict__ src, __nv_bfloat16* __restrict__ hi,
         __nv_bfloat16* __restrict__ lo, int R, int C)
{
    __shared__ float t[32][33];
    const long long base = (long long)blockIdx.z * R * C;
    const int c0 = blockIdx.x << 5, r0 = blockIdx.y << 5;
    const int tx = threadIdx.x & 31, ty = threadIdx.x >> 5;
    #pragma unroll
    for (int i = 0; i < 4; ++i) {
        int r = r0 + ty + i * 8;
        t[ty + i * 8][tx] = src[base + (long long)r * C + c0 + tx];
    }
    __syncthreads();
    #pragma unroll
    for (int i = 0; i < 4; ++i) {
        int c = c0 + ty + i * 8;
        float v = t[tx][ty + i * 8];
        __nv_bfloat16 h = __float2bfloat16(v);
        long long o = base + (long long)c * R + r0 + tx;
        hi[o] = h;
        lo[o] = __float2bfloat16(v - __bfloat162float(h));
    }
}

// ===========================================================================
// Elementwise bf16 hi/lo split (vectorized by 4)
// ===========================================================================
__global__ void __launch_bounds__(256)
split_k(const float* __restrict__ x, __nv_bfloat16* __restrict__ hi,
        __nv_bfloat16* __restrict__ lo, int n4)
{
    int i = blockIdx.x * 256 + threadIdx.x;
    if (i >= n4) return;
    float4 v = ((const float4*)x)[i];
    __nv_bfloat16 h[4], l[4];
    h[0] = __float2bfloat16(v.x); l[0] = __float2bfloat16(v.x - __bfloat162float(h[0]));
    h[1] = __float2bfloat16(v.y); l[1] = __float2bfloat16(v.y - __bfloat162float(h[1]));
    h[2] = __float2bfloat16(v.z); l[2] = __float2bfloat16(v.z - __bfloat162float(h[2]));
    h[3] = __float2bfloat16(v.w); l[3] = __float2bfloat16(v.w - __bfloat162float(h[3]));
    *(uint2*)(hi + 4 * (size_t)i) = *(uint2*)h;
    *(uint2*)(lo + 4 * (size_t)i) = *(uint2*)l;
}

// ===========================================================================
// LayerNorm over M=1024, emitting bf16 hi/lo split. One block per row.
// ===========================================================================
__global__ void __launch_bounds__(256)
layernorm_split_k(const float* __restrict__ x, const float* __restrict__ g,
                  const float* __restrict__ b,
                  __nv_bfloat16* __restrict__ hi, __nv_bfloat16* __restrict__ lo)
{
    const int row = blockIdx.x;
    const float* xp = x + (size_t)row * M_;
    const int c = threadIdx.x << 2;
    float4 d = *(const float4*)(xp + c);
    float s  = d.x + d.y + d.z + d.w;
    float ss = d.x * d.x + d.y * d.y + d.z * d.z + d.w * d.w;
    s  = block_sum(s);
    ss = block_sum(ss);
    const float mean = s * (1.f / M_);
    const float var  = ss * (1.f / M_) - mean * mean;
    const float inv  = rsqrtf(var + 1e-5f);
    float4 g4 = *(const float4*)(g + c);
    float4 b4 = *(const float4*)(b + c);
    float o[4];
    o[0] = (d.x - mean) * inv * g4.x + b4.x;
    o[1] = (d.y - mean) * inv * g4.y + b4.y;
    o[2] = (d.z - mean) * inv * g4.z + b4.z;
    o[3] = (d.w - mean) * inv * g4.w + b4.w;
    __nv_bfloat16 h[4], l[4];
    #pragma unroll
    for (int i = 0; i < 4; ++i) {
        h[i] = __float2bfloat16(o[i]);
        l[i] = __float2bfloat16(o[i] - __bfloat162float(h[i]));
    }
    *(uint2*)(hi + (size_t)row * M_ + c) = *(uint2*)h;
    *(uint2*)(lo + (size_t)row * M_ + c) = *(uint2*)l;
}

// ===========================================================================
// Masked softmax over T=1024 -> bf16 hi/lo split output. One block per row.
// ===========================================================================
__global__ void __launch_bounds__(256)
attn_softmax_split_k(const float* __restrict__ att,
                     const float* __restrict__ tmask, const float* __restrict__ qtmask,
                     __nv_bfloat16* __restrict__ atth, __nv_bfloat16* __restrict__ attl)
{
    const int row = blockIdx.x;
    const int b = row >> 13;
    const int q = row & (Q_ - 1);
    const float* p = att + (size_t)row * T_;
    const float inv = 0.08838834764831845f;   // 1/sqrt(128)
    float vals[4];
    float mx = -3.0e38f;
    #pragma unroll
    for (int i = 0; i < 4; ++i) {
        int t = threadIdx.x + (i << 8);
        float m = tmask ? tmask[b * T_ + t] : 0.f;
        if (qtmask) m = fmaxf(m, qtmask[((size_t)(b * Q_ + q)) * T_ + t]);
        float v = (p[t] - m * 1e6f) * inv;
        vals[i] = v;
        mx = fmaxf(mx, v);
    }
    mx = block_max(mx);
    float s = 0.f;
    #pragma unroll
    for (int i = 0; i < 4; ++i) { vals[i] = expf(vals[i] - mx); s += vals[i]; }
    s = block_sum(s);
    const float r = 1.f / s;
    #pragma unroll
    for (int i = 0; i < 4; ++i) {
        float v = vals[i] * r;
        __nv_bfloat16 h = __float2bfloat16(v);
        size_t o = (size_t)row * T_ + threadIdx.x + (i << 8);
        atth[o] = h;
        attl[o] = __float2bfloat16(v - __bfloat162float(h));
    }
}

// ===========================================================================
// bf16x3 mma.sync GEMM:
//   C[Mrows x N] = A[Mrows x K] * B[N x K]^T  (both split into hi/lo bf16)
// CTA tile 128x128, BK=32, 8 warps (warp tile 32x64), cp.async double buffer.
// Batch over blockIdx.z: (b,h) = (z>>3, z&7) with independent strides.
// EPI: 0 none | 1 resid+rowmask | 2 bias+relu | 3 bias+resid+rowmask
// OUT: 0 fp32 C | 1 bf16 hi/lo pair (Ch, Cl)
// ===========================================================================
#define PITCH_B 80                 // bytes per smem tile row (32 bf16 + 8 pad)
#define TILE_B  (128 * PITCH_B)    // 10240 B
#define STAGE_B (4 * TILE_B)       // Ah, Al, Bh, Bl
#define MG_SMEM (2 * STAGE_B)      // 81920 B

__device__ __forceinline__ void mg_load(
    uint32_t sb, const __nv_bfloat16* __restrict__ Ah, const __nv_bfloat16* __restrict__ Al,
    const __nv_bfloat16* __restrict__ Bh, const __nv_bfloat16* __restrict__ Bl,
    int tid, int m0, int n0, int lda, int ldb, int koff)
{
    int seg = tid;
    #pragma unroll
    for (int i = 0; i < 2; ++i, seg += 256) {
        int r = seg >> 2, s = seg & 3;
        uint32_t d = sb + r * PITCH_B + s * 16;
        const long long g = (long long)(m0 + r) * lda + koff + s * 8;
        cp16(d,          Ah + g);
        cp16(d + TILE_B, Al + g);
    }
    seg = tid;
    #pragma unroll
    for (int i = 0; i < 2; ++i, seg += 256) {
        int r = seg >> 2, s = seg & 3;
        uint32_t d = sb + 2 * TILE_B + r * PITCH_B + s * 16;
        const long long g = (long long)(n0 + r) * ldb + koff + s * 8;
        cp16(d,          Bh + g);
        cp16(d + TILE_B, Bl + g);
    }
    cp_commit();
}

template <int EPI, int OUT>
__global__ void __launch_bounds__(256)
mgemm_k(const __nv_bfloat16* __restrict__ Ah, const __nv_bfloat16* __restrict__ Al,
        long long sAb, long long sAh2, int lda,
        const __nv_bfloat16* __restrict__ Bh, const __nv_bfloat16* __restrict__ Bl,
        long long sBb, long long sBh2, int ldb,
        float* Cf, __nv_bfloat16* Ch, __nv_bfloat16* Cl,
        long long sCb, long long sCh2, int ldc,
        const float* __restrict__ resid, const float* __restrict__ bias,
        const float* __restrict__ rowmask, int Kdim)
{
    extern __shared__ __align__(128) char smem[];
    const int tid = threadIdx.x, wid = tid >> 5, lane = tid & 31;
    const int z = blockIdx.z;
    Ah += (long long)(z >> 3) * sAb + (long long)(z & 7) * sAh2;
    Al += (long long)(z >> 3) * sAb + (long long)(z & 7) * sAh2;
    Bh += (long long)(z >> 3) * sBb + (long long)(z & 7) * sBh2;
    Bl += (long long)(z >> 3) * sBb + (long long)(z & 7) * sBh2;
    const long long coff = (long long)(z >> 3) * sCb + (long long)(z & 7) * sCh2;
    if (OUT == 0) Cf += coff; else { Ch += coff; Cl += coff; }

    const int m0 = blockIdx.y << 7, n0 = blockIdx.x << 7;
    const int wm = (wid >> 1) << 5;       // warp row offset (0..96)
    const int wn = (wid & 1) << 6;        // warp col offset (0 or 64)
    const uint32_t sb0 = smem_to_u32(smem);

    // ldmatrix per-lane address offsets (bytes)
    const uint32_t aoff = ((lane & 7) + ((lane >> 3) & 1) * 8) * PITCH_B + ((lane >> 4) & 1) * 16;
    const uint32_t boff = ((lane & 7) + ((lane >> 4) & 1) * 8) * PITCH_B + ((lane >> 3) & 1) * 16;

    float acc[2][8][4];
    #pragma unroll
    for (int i = 0; i < 2; ++i)
        #pragma unroll
        for (int j = 0; j < 8; ++j)
            #pragma unroll
            for (int k = 0; k < 4; ++k) acc[i][j][k] = 0.f;

    const int NC = Kdim >> 5;
    mg_load(sb0, Ah, Al, Bh, Bl, tid, m0, n0, lda, ldb, 0);

    for (int kt = 0; kt < NC; ++kt) {
        if (kt + 1 < NC) {
            mg_load(sb0 + (uint32_t)((kt + 1) & 1) * STAGE_B,
                    Ah, Al, Bh, Bl, tid, m0, n0, lda, ldb, (kt + 1) << 5);
            cp_wait1();
        } else {
            cp_wait0();
        }
        __syncthreads();

        const uint32_t sA = sb0 + (uint32_t)(kt & 1) * STAGE_B;
        const uint32_t sB = sA + 2 * TILE_B;
        #pragma unroll
        for (int k0 = 0; k0 < 2; ++k0) {
            uint32_t a_hi[2][4], a_lo[2][4], b_hi[4][4], b_lo[4][4];
            #pragma unroll
            for (int mf = 0; mf < 2; ++mf) {
                uint32_t ad = sA + (wm + mf * 16) * PITCH_B + k0 * 32 + aoff;
                ldsm_x4(a_hi[mf], ad);
                ldsm_x4(a_lo[mf], ad + TILE_B);
            }
            #pragma unroll
            for (int np = 0; np < 4; ++np) {
                uint32_t bd = sB + (wn + np * 16) * PITCH_B + k0 * 32 + boff;
                ldsm_x4(b_hi[np], bd);
                ldsm_x4(b_lo[np], bd + TILE_B);
            }
            #pragma unroll
            for (int mf = 0; mf < 2; ++mf)
                #pragma unroll
                for (int np = 0; np < 4; ++np) {
                    mma16816(acc[mf][2 * np],     a_hi[mf], &b_hi[np][0]);
                    mma16816(acc[mf][2 * np + 1], a_hi[mf], &b_hi[np][2]);
                    mma16816(acc[mf][2 * np],     a_hi[mf], &b_lo[np][0]);
                    mma16816(acc[mf][2 * np + 1], a_hi[mf], &b_lo[np][2]);
                    mma16816(acc[mf][2 * np],     a_lo[mf], &b_hi[np][0]);
                    mma16816(acc[mf][2 * np + 1], a_lo[mf], &b_hi[np][2]);
                }
        }
        __syncthreads();
    }

    // Epilogue: direct per-thread stores (float2 / bf16x2 pairs)
    const int lr = lane >> 2, lc2 = (lane & 3) << 1;
    #pragma unroll
    for (int mf = 0; mf < 2; ++mf) {
        #pragma unroll
        for (int h2 = 0; h2 < 2; ++h2) {
            const long long r = m0 + wm + mf * 16 + h2 * 8 + lr;
            float mfac = 1.f;
            if (EPI == 1 || EPI == 3) mfac = 1.f - rowmask[r];
            #pragma unroll
            for (int nf = 0; nf < 8; ++nf) {
                float v0 = acc[mf][nf][h2 * 2 + 0];
                float v1 = acc[mf][nf][h2 * 2 + 1];
                const long long c = n0 + wn + nf * 8 + lc2;
                if (EPI >= 2) { v0 += bias[c]; v1 += bias[c + 1]; }
                if (EPI == 2) { v0 = fmaxf(v0, 0.f); v1 = fmaxf(v1, 0.f); }
                if (EPI == 1 || EPI == 3) {
                    float2 rs = *(const float2*)(resid + r * ldc + c);
                    v0 = rs.x + v0 * mfac;
                    v1 = rs.y + v1 * mfac;
                }
                if (OUT == 0) {
                    float2 o; o.x = v0; o.y = v1;
                    *(float2*)(Cf + r * ldc + c) = o;
                } else {
                    __nv_bfloat16 h0 = __float2bfloat16(v0), h1 = __float2bfloat16(v1);
                    __nv_bfloat162 hh, ll;
                    hh.x = h0; hh.y = h1;
                    ll.x = __float2bfloat16(v0 - __bfloat162float(h0));
                    ll.y = __float2bfloat16(v1 - __bfloat162float(h1));
                    *(__nv_bfloat162*)(Ch + r * ldc + c) = hh;
                    *(__nv_bfloat162*)(Cl + r * ldc + c) = ll;
                }
            }
        }
    }
}

// ===========================================================================
// Host orchestration
// ===========================================================================
extern "C" void kernel_launch(void* const* d_in, const int* in_sizes, int n_in,
                              void* d_out, int out_size)
{
    (void)in_sizes; (void)n_in; (void)out_size;

    const float* enc_out = (const float*)d_in[0];
    const float* x       = (const float*)d_in[1];
    const float* pmask   = (const float*)d_in[2];
    const float* qtself  = (const float*)d_in[3];
    const float* qtcross = (const float*)d_in[4];
    const float* swq = (const float*)d_in[5];
    const float* swk = (const float*)d_in[6];
    const float* swv = (const float*)d_in[7];
    const float* swo = (const float*)d_in[8];
    const float* cwq = (const float*)d_in[9];
    const float* cwk = (const float*)d_in[10];
    const float* cwv = (const float*)d_in[11];
    const float* cwo = (const float*)d_in[12];
    const float* w1  = (const float*)d_in[13];
    const float* b1  = (const float*)d_in[14];
    const float* w2  = (const float*)d_in[15];
    const float* b2  = (const float*)d_in[16];
    const float* ln1g = (const float*)d_in[17];
    const float* ln1b = (const float*)d_in[18];
    const float* ln2g = (const float*)d_in[19];
    const float* ln2b = (const float*)d_in[20];
    const float* ln3g = (const float*)d_in[21];
    const float* ln3b = (const float*)d_in[22];

    float *hb, *ab;
    cudaGetSymbolAddress((void**)&hb, g_h);
    cudaGetSymbolAddress((void**)&ab, g_att);

    __nv_bfloat16 *wqs_h, *wqs_l, *wks_h, *wks_l, *wvs_h, *wvs_l;
    __nv_bfloat16 *wqc_h, *wqc_l, *wkc_h, *wkc_l, *wvc_h, *wvc_l;
    __nv_bfloat16 *wos_h, *wos_l, *woc_h, *woc_l, *w1h, *w1l, *w2h, *w2l;
    __nv_bfloat16 *nh, *nl, *qh, *ql, *kh, *kl, *vth, *vtl, *ph, *pl;
    __nv_bfloat16 *eh, *el, *sh, *sl, *ath, *atl;
    cudaGetSymbolAddress((void**)&wqs_h, g_wqs_h); cudaGetSymbolAddress((void**)&wqs_l, g_wqs_l);
    cudaGetSymbolAddress((void**)&wks_h, g_wks_h); cudaGetSymbolAddress((void**)&wks_l, g_wks_l);
    cudaGetSymbolAddress((void**)&wvs_h, g_wvs_h); cudaGetSymbolAddress((void**)&wvs_l, g_wvs_l);
    cudaGetSymbolAddress((void**)&wqc_h, g_wqc_h); cudaGetSymbolAddress((void**)&wqc_l, g_wqc_l);
    cudaGetSymbolAddress((void**)&wkc_h, g_wkc_h); cudaGetSymbolAddress((void**)&wkc_l, g_wkc_l);
    cudaGetSymbolAddress((void**)&wvc_h, g_wvc_h); cudaGetSymbolAddress((void**)&wvc_l, g_wvc_l);
    cudaGetSymbolAddress((void**)&wos_h, g_wos_h); cudaGetSymbolAddress((void**)&wos_l, g_wos_l);
    cudaGetSymbolAddress((void**)&woc_h, g_woc_h); cudaGetSymbolAddress((void**)&woc_l, g_woc_l);
    cudaGetSymbolAddress((void**)&w1h, g_w1_h);    cudaGetSymbolAddress((void**)&w1l, g_w1_l);
    cudaGetSymbolAddress((void**)&w2h, g_w2_h);    cudaGetSymbolAddress((void**)&w2l, g_w2_l);
    cudaGetSymbolAddress((void**)&nh, g_nh);   cudaGetSymbolAddress((void**)&nl, g_nl);
    cudaGetSymbolAddress((void**)&qh, g_qh);   cudaGetSymbolAddress((void**)&ql, g_ql);
    cudaGetSymbolAddress((void**)&kh, g_kh);   cudaGetSymbolAddress((void**)&kl, g_kl);
    cudaGetSymbolAddress((void**)&vth, g_vth); cudaGetSymbolAddress((void**)&vtl, g_vtl);
    cudaGetSymbolAddress((void**)&ph, g_ph);   cudaGetSymbolAddress((void**)&pl, g_pl);
    cudaGetSymbolAddress((void**)&eh, g_eh);   cudaGetSymbolAddress((void**)&el, g_el);
    cudaGetSymbolAddress((void**)&sh, g_sh);   cudaGetSymbolAddress((void**)&sl, g_sl);
    cudaGetSymbolAddress((void**)&ath, g_ath); cudaGetSymbolAddress((void**)&atl, g_atl);

    cudaFuncSetAttribute(mgemm_k<0,0>, cudaFuncAttributeMaxDynamicSharedMemorySize, MG_SMEM);
    cudaFuncSetAttribute(mgemm_k<0,1>, cudaFuncAttributeMaxDynamicSharedMemorySize, MG_SMEM);
    cudaFuncSetAttribute(mgemm_k<1,0>, cudaFuncAttributeMaxDynamicSharedMemorySize, MG_SMEM);
    cudaFuncSetAttribute(mgemm_k<2,1>, cudaFuncAttributeMaxDynamicSharedMemorySize, MG_SMEM);
    cudaFuncSetAttribute(mgemm_k<3,0>, cudaFuncAttributeMaxDynamicSharedMemorySize, MG_SMEM);

    // --- weight prep: transpose + bf16 split ---
    {
        dim3 gq(K_ / 32, M_ / 32, L_ * H_);          // qkv: per (l,h) [M][128] -> [128][M]
        tsplit_k<<<gq, 256>>>(swq, wqs_h, wqs_l, M_, K_);
        tsplit_k<<<gq, 256>>>(swk, wks_h, wks_l, M_, K_);
        tsplit_k<<<gq, 256>>>(swv, wvs_h, wvs_l, M_, K_);
        tsplit_k<<<gq, 256>>>(cwq, wqc_h, wqc_l, M_, K_);
        tsplit_k<<<gq, 256>>>(cwk, wkc_h, wkc_l, M_, K_);
        tsplit_k<<<gq, 256>>>(cwv, wvc_h, wvc_l, M_, K_);
        dim3 go(M_ / 32, (H_ * V_) / 32, L_);        // wo: per l [H*V][M] -> [M][H*V]
        tsplit_k<<<go, 256>>>(swo, wos_h, wos_l, H_ * V_, M_);
        tsplit_k<<<go, 256>>>(cwo, woc_h, woc_l, H_ * V_, M_);
        dim3 g1(F_ / 32, M_ / 32, L_);               // w1: per l [M][F] -> [F][M]
        tsplit_k<<<g1, 256>>>(w1, w1h, w1l, M_, F_);
        dim3 g2(M_ / 32, F_ / 32, L_);               // w2: per l [F][M] -> [M][F]
        tsplit_k<<<g2, 256>>>(w2, w2h, w2l, F_, M_);
    }
    split_k<<<B_ * T_ * M_ / 4 / 256, 256>>>(enc_out, eh, el, B_ * T_ * M_ / 4);

    cudaMemcpyAsync(hb, x, (size_t)BQ_ * M_ * sizeof(float), cudaMemcpyDeviceToDevice);

    const dim3 gP (M_ / 128, BQ_ / 128, 1);          // (8,32)   proj / FFN2
    const dim3 gVT(BQ_ / 128, M_ / 128, 1);          // (32,8)   vT
    const dim3 gQK(T_ / 128, Q_ / 128, B_ * H_);     // (8,8,32)
    const dim3 gAV(V_ / 128, Q_ / 128, B_ * H_);     // (1,8,32)
    const dim3 gF1(F_ / 128, BQ_ / 128, 1);          // (32,32)

    const long long sQb   = (long long)Q_ * M_;      // b-stride in q/k/pre
    const long long sAttB = (long long)H_ * Q_ * T_;
    const long long sAttH = (long long)Q_ * T_;
    const long long sVTb  = 1024;                    // b-col offset in vT
    const long long sVTh  = (long long)128 * BQ_;    // h-row offset in vT
    const size_t wL  = 1048576;
    const size_t wLF = 4194304;

    for (int l = 0; l < L_; ++l) {
        for (int pass = 0; pass < 2; ++pass) {
            const bool self = (pass == 0);
            const float* lng = self ? ln1g : ln2g;
            const float* lnb = self ? ln1b : ln2b;
            __nv_bfloat16* wq_h = (self ? wqs_h : wqc_h) + l * wL;
            __nv_bfloat16* wq_l = (self ? wqs_l : wqc_l) + l * wL;
            __nv_bfloat16* wk_h = (self ? wks_h : wkc_h) + l * wL;
            __nv_bfloat16* wk_l = (self ? wks_l : wkc_l) + l * wL;
            __nv_bfloat16* wv_h = (self ? wvs_h : wvc_h) + l * wL;
            __nv_bfloat16* wv_l = (self ? wvs_l : wvc_l) + l * wL;
            __nv_bfloat16* wo_h = (self ? wos_h : woc_h) + l * wL;
            __nv_bfloat16* wo_l = (self ? wos_l : woc_l) + l * wL;
            __nv_bfloat16* kv_h = self ? nh : eh;
            __nv_bfloat16* kv_l = self ? nl : el;

            layernorm_split_k<<<BQ_, 256>>>(hb, lng + l * M_, lnb + l * M_, nh, nl);
            // q = n * Wq^T   -> split
            mgemm_k<0,1><<<gP, 256, MG_SMEM>>>(nh, nl, 0, 0, M_,
                                               wq_h, wq_l, 0, 0, M_,
                                               nullptr, qh, ql, 0, 0, M_,
                                               nullptr, nullptr, nullptr, M_);
            // k = kv * Wk^T  -> split
            mgemm_k<0,1><<<gP, 256, MG_SMEM>>>(kv_h, kv_l, 0, 0, M_,
                                               wk_h, wk_l, 0, 0, M_,
                                               nullptr, kh, kl, 0, 0, M_,
                                               nullptr, nullptr, nullptr, M_);
            // vT = Wv * kv^T -> split  [1024 rows (h*d)][4096 cols (b*t)]
            mgemm_k<0,1><<<gVT, 256, MG_SMEM>>>(wv_h, wv_l, 0, 0, M_,
                                                kv_h, kv_l, 0, 0, M_,
                                                nullptr, vth, vtl, 0, 0, BQ_,
                                                nullptr, nullptr, nullptr, M_);
            // logits = q k^T (batched over b,h) -> fp32
            mgemm_k<0,0><<<gQK, 256, MG_SMEM>>>(qh, ql, sQb, 128, M_,
                                                kh, kl, sQb, 128, M_,
                                                ab, nullptr, nullptr, sAttB, sAttH, T_,
                                                nullptr, nullptr, nullptr, K_);
            attn_softmax_split_k<<<B_ * H_ * Q_, 256>>>(ab, self ? pmask : nullptr,
                                                        self ? qtself : qtcross, ath, atl);
            // pre = att * vT^T (batched) -> split
            mgemm_k<0,1><<<gAV, 256, MG_SMEM>>>(ath, atl, sAttB, sAttH, T_,
                                                vth, vtl, sVTb, sVTh, BQ_,
                                                nullptr, ph, pl, sQb, 128, M_,
                                                nullptr, nullptr, nullptr, T_);
            // h += (pre * Wo^T) * (1 - mask)
            mgemm_k<1,0><<<gP, 256, MG_SMEM>>>(ph, pl, 0, 0, M_,
                                               wo_h, wo_l, 0, 0, M_,
                                               hb, nullptr, nullptr, 0, 0, M_,
                                               hb, nullptr, pmask, M_);
        }

        // ---- FFN ----
        layernorm_split_k<<<BQ_, 256>>>(hb, ln3g + l * M_, ln3b + l * M_, nh, nl);
        mgemm_k<2,1><<<gF1, 256, MG_SMEM>>>(nh, nl, 0, 0, M_,
                                            w1h + l * wLF, w1l + l * wLF, 0, 0, M_,
                                            nullptr, sh, sl, 0, 0, F_,
                                            nullptr, b1 + l * F_, nullptr, M_);
        mgemm_k<3,0><<<gP, 256, MG_SMEM>>>(sh, sl, 0, 0, F_,
                                           w2h + l * wLF, w2l + l * wLF, 0, 0, F_,
                                           hb, nullptr, nullptr, 0, 0, M_,
                                           hb, b2 + l * M_, pmask, F_);
    }

    cudaMemcpyAsync(d_out, hb, (size_t)BQ_ * M_ * sizeof(float),
                    cudaMemcpyDeviceToDevice);
}

// round 5
// speedup vs baseline: 2.5859x; 1.1025x over previous
#include <cuda_runtime.h>
#include <cuda_bf16.h>
#include <cstdint>
#include <cstddef>

// Problem constants
#define L_  6
#define H_  8
#define M_  1024
#define K_  128
#define V_  128
#define F_  4096
#define B_  4
#define Q_  1024
#define T_  1024
#define BQ_ 4096   // B_*Q_

// ===========================================================================
// Low-level helpers (base PTX only — no sm_103a-specific instructions)
// ===========================================================================
__device__ __forceinline__ uint32_t smem_to_u32(const void* p) {
    uint32_t a;
    asm("{ .reg .u64 t; cvta.to.shared.u64 t, %1; cvt.u32.u64 %0, t; }"
        : "=r"(a) : "l"(p));
    return a;
}

__device__ __forceinline__ void cp16(uint32_t dst, const void* src) {
    asm volatile("cp.async.cg.shared.global [%0], [%1], 16;"
                 :: "r"(dst), "l"(__cvta_generic_to_global(src)));
}
__device__ __forceinline__ void cp_commit() { asm volatile("cp.async.commit_group;" ::: "memory"); }
__device__ __forceinline__ void cp_wait0()  { asm volatile("cp.async.wait_group 0;" ::: "memory"); }
__device__ __forceinline__ void cp_wait1()  { asm volatile("cp.async.wait_group 1;" ::: "memory"); }

__device__ __forceinline__ void ldsm_x4(uint32_t* r, uint32_t addr) {
    asm volatile("ldmatrix.sync.aligned.m8n8.x4.shared.b16 {%0,%1,%2,%3}, [%4];"
                 : "=r"(r[0]), "=r"(r[1]), "=r"(r[2]), "=r"(r[3]) : "r"(addr));
}

__device__ __forceinline__ void mma16816(float* d, const uint32_t* a, const uint32_t* b) {
    asm volatile(
        "mma.sync.aligned.m16n8k16.row.col.f32.bf16.bf16.f32 "
        "{%0,%1,%2,%3}, {%4,%5,%6,%7}, {%8,%9}, {%0,%1,%2,%3};"
        : "+f"(d[0]), "+f"(d[1]), "+f"(d[2]), "+f"(d[3])
        : "r"(a[0]), "r"(a[1]), "r"(a[2]), "r"(a[3]), "r"(b[0]), "r"(b[1]));
}

__device__ __forceinline__ uint32_t pack_bf162(float a, float b) {
    __nv_bfloat162 t;
    t.x = __float2bfloat16(a);
    t.y = __float2bfloat16(b);
    return *(uint32_t*)&t;
}

// ===========================================================================
// Scratch (device globals; no runtime allocation allowed)
// ===========================================================================
__device__ float g_h[(size_t)BQ_ * M_];

// bf16 split weights: [N][K] k-major, per layer contiguous
#define WQKV_SZ ((size_t)L_ * 1048576)   // L * (H*128) * M
#define WFF_SZ  ((size_t)L_ * 4194304)   // L * F * M
__device__ __align__(256) __nv_bfloat16 g_wqs_h[WQKV_SZ], g_wqs_l[WQKV_SZ];
__device__ __align__(256) __nv_bfloat16 g_wks_h[WQKV_SZ], g_wks_l[WQKV_SZ];
__device__ __align__(256) __nv_bfloat16 g_wvs_h[WQKV_SZ], g_wvs_l[WQKV_SZ];
__device__ __align__(256) __nv_bfloat16 g_wqc_h[WQKV_SZ], g_wqc_l[WQKV_SZ];
__device__ __align__(256) __nv_bfloat16 g_wkc_h[WQKV_SZ], g_wkc_l[WQKV_SZ];
__device__ __align__(256) __nv_bfloat16 g_wvc_h[WQKV_SZ], g_wvc_l[WQKV_SZ];
__device__ __align__(256) __nv_bfloat16 g_wos_h[WQKV_SZ], g_wos_l[WQKV_SZ];
__device__ __align__(256) __nv_bfloat16 g_woc_h[WQKV_SZ], g_woc_l[WQKV_SZ];
__device__ __align__(256) __nv_bfloat16 g_w1_h[WFF_SZ],  g_w1_l[WFF_SZ];
__device__ __align__(256) __nv_bfloat16 g_w2_h[WFF_SZ],  g_w2_l[WFF_SZ];

// bf16 split activations
__device__ __align__(256) __nv_bfloat16 g_nh [(size_t)BQ_ * M_], g_nl [(size_t)BQ_ * M_];
__device__ __align__(256) __nv_bfloat16 g_qh [(size_t)BQ_ * M_], g_ql [(size_t)BQ_ * M_];
__device__ __align__(256) __nv_bfloat16 g_kh [(size_t)BQ_ * M_], g_kl [(size_t)BQ_ * M_];
__device__ __align__(256) __nv_bfloat16 g_vth[(size_t)M_ * BQ_], g_vtl[(size_t)M_ * BQ_];
__device__ __align__(256) __nv_bfloat16 g_ph [(size_t)BQ_ * M_], g_pl [(size_t)BQ_ * M_];
__device__ __align__(256) __nv_bfloat16 g_eh [(size_t)B_ * T_ * M_], g_el [(size_t)B_ * T_ * M_];
__device__ __align__(256) __nv_bfloat16 g_sh [(size_t)BQ_ * F_], g_sl [(size_t)BQ_ * F_];

// mask bias arrays: [B][Q][T] bf16 = max(tmask,qtmask) * (-1e6/sqrt(128))
__device__ __align__(256) __nv_bfloat16 g_bias_s[(size_t)B_ * Q_ * T_];
__device__ __align__(256) __nv_bfloat16 g_bias_c[(size_t)B_ * Q_ * T_];

// ===========================================================================
// Block reductions (blockDim.x == 256)
// ===========================================================================
__device__ __forceinline__ float block_sum(float v) {
    __shared__ float sh[8];
    #pragma unroll
    for (int o = 16; o > 0; o >>= 1) v += __shfl_xor_sync(0xffffffffu, v, o);
    __syncthreads();
    if ((threadIdx.x & 31) == 0) sh[threadIdx.x >> 5] = v;
    __syncthreads();
    float t = 0.f;
    #pragma unroll
    for (int i = 0; i < 8; ++i) t += sh[i];
    return t;
}

// ===========================================================================
// Batched transpose + bf16 hi/lo split: [batch][R][C] fp32 -> [batch][C][R]
// ===========================================================================
__global__ void __launch_bounds__(256)
tsplit_k(const float* __restrict__ src, __nv_bfloat16* __restrict__ hi,
         __nv_bfloat16* __restrict__ lo, int R, int C)
{
    __shared__ float t[32][33];
    const long long base = (long long)blockIdx.z * R * C;
    const int c0 = blockIdx.x << 5, r0 = blockIdx.y << 5;
    const int tx = threadIdx.x & 31, ty = threadIdx.x >> 5;
    #pragma unroll
    for (int i = 0; i < 4; ++i) {
        int r = r0 + ty + i * 8;
        t[ty + i * 8][tx] = src[base + (long long)r * C + c0 + tx];
    }
    __syncthreads();
    #pragma unroll
    for (int i = 0; i < 4; ++i) {
        int c = c0 + ty + i * 8;
        float v = t[tx][ty + i * 8];
        __nv_bfloat16 h = __float2bfloat16(v);
        long long o = base + (long long)c * R + r0 + tx;
        hi[o] = h;
        lo[o] = __float2bfloat16(v - __bfloat162float(h));
    }
}

// ===========================================================================
// Elementwise bf16 hi/lo split (vectorized by 4)
// ===========================================================================
__global__ void __launch_bounds__(256)
split_k(const float* __restrict__ x, __nv_bfloat16* __restrict__ hi,
        __nv_bfloat16* __restrict__ lo, int n4)
{
    int i = blockIdx.x * 256 + threadIdx.x;
    if (i >= n4) return;
    float4 v = ((const float4*)x)[i];
    __nv_bfloat16 h[4], l[4];
    h[0] = __float2bfloat16(v.x); l[0] = __float2bfloat16(v.x - __bfloat162float(h[0]));
    h[1] = __float2bfloat16(v.y); l[1] = __float2bfloat16(v.y - __bfloat162float(h[1]));
    h[2] = __float2bfloat16(v.z); l[2] = __float2bfloat16(v.z - __bfloat162float(h[2]));
    h[3] = __float2bfloat16(v.w); l[3] = __float2bfloat16(v.w - __bfloat162float(h[3]));
    *(uint2*)(hi + 4 * (size_t)i) = *(uint2*)h;
    *(uint2*)(lo + 4 * (size_t)i) = *(uint2*)l;
}

// ===========================================================================
// Mask bias build: out[b,q,t] = max(tmask[b,t], qtmask[b,q,t]) * (-1e6/sqrt(128))
// 2 elements per thread, B*Q*T/2/256 blocks.
// ===========================================================================
__global__ void __launch_bounds__(256)
bias_build_k(const float* __restrict__ tmask, const float* __restrict__ qtmask,
             __nv_bfloat16* __restrict__ out)
{
    const long long i2 = ((long long)blockIdx.x * 256 + threadIdx.x) * 2;
    const int t = (int)(i2 & 1023);
    const int b = (int)(i2 >> 20);
    float m0 = qtmask[i2], m1 = qtmask[i2 + 1];
    if (tmask) {
        m0 = fmaxf(m0, tmask[b * 1024 + t]);
        m1 = fmaxf(m1, tmask[b * 1024 + t + 1]);
    }
    const float c = -88388.34765f;   // -1e6 / sqrt(128)
    __nv_bfloat162 o;
    o.x = __float2bfloat16(m0 * c);
    o.y = __float2bfloat16(m1 * c);
    *(__nv_bfloat162*)(out + i2) = o;
}

// ===========================================================================
// LayerNorm over M=1024, emitting bf16 hi/lo split. One block per row.
// ===========================================================================
__global__ void __launch_bounds__(256)
layernorm_split_k(const float* __restrict__ x, const float* __restrict__ g,
                  const float* __restrict__ b,
                  __nv_bfloat16* __restrict__ hi, __nv_bfloat16* __restrict__ lo)
{
    const int row = blockIdx.x;
    const float* xp = x + (size_t)row * M_;
    const int c = threadIdx.x << 2;
    float4 d = *(const float4*)(xp + c);
    float s  = d.x + d.y + d.z + d.w;
    float ss = d.x * d.x + d.y * d.y + d.z * d.z + d.w * d.w;
    s  = block_sum(s);
    ss = block_sum(ss);
    const float mean = s * (1.f / M_);
    const float var  = ss * (1.f / M_) - mean * mean;
    const float inv  = rsqrtf(var + 1e-5f);
    float4 g4 = *(const float4*)(g + c);
    float4 b4 = *(const float4*)(b + c);
    float o[4];
    o[0] = (d.x - mean) * inv * g4.x + b4.x;
    o[1] = (d.y - mean) * inv * g4.y + b4.y;
    o[2] = (d.z - mean) * inv * g4.z + b4.z;
    o[3] = (d.w - mean) * inv * g4.w + b4.w;
    __nv_bfloat16 h[4], l[4];
    #pragma unroll
    for (int i = 0; i < 4; ++i) {
        h[i] = __float2bfloat16(o[i]);
        l[i] = __float2bfloat16(o[i] - __bfloat162float(h[i]));
    }
    *(uint2*)(hi + (size_t)row * M_ + c) = *(uint2*)h;
    *(uint2*)(lo + (size_t)row * M_ + c) = *(uint2*)l;
}

// ===========================================================================
// Fused flash attention (bf16x3 everywhere, fp32 softmax/accum).
// CTA: 64 q-rows of one (b,h); 4 warps; warp tile m=16, n covers all 64 t.
// Q tile resident in registers; K/V chunks (64 t) single-buffered in smem;
// fully-masked chunks skipped via __syncthreads_or vote on the bias tile.
// Inputs: qh/ql, kh/kl [b*t][h*128+d]; vth/vtl = V^T [h*128+d][b*1024+t].
// Output: ph/pl [b*q][h*128+d] split bf16.
// ===========================================================================
#define FL_QP  272                 // Q/K smem pitch bytes (128 bf16 + pad)
#define FL_VP  144                 // V smem pitch bytes  (64 bf16 + pad)
#define FL_SQH 0
#define FL_SQL 17408
#define FL_SKH 34816
#define FL_SKL 52224
#define FL_SVH 69632
#define FL_SVL 88064
#define FL_SMEM 106496

__global__ void __launch_bounds__(128)
flash_k(const __nv_bfloat16* __restrict__ qh, const __nv_bfloat16* __restrict__ ql,
        const __nv_bfloat16* __restrict__ kh, const __nv_bfloat16* __restrict__ kl,
        const __nv_bfloat16* __restrict__ vth, const __nv_bfloat16* __restrict__ vtl,
        const __nv_bfloat16* __restrict__ bias,
        __nv_bfloat16* __restrict__ ph, __nv_bfloat16* __restrict__ pl)
{
    extern __shared__ __align__(128) char smem[];
    const int tid = threadIdx.x, wid = tid >> 5, lane = tid & 31;
    const int bh = blockIdx.y, b = bh >> 3, h = bh & 7;
    const int q0 = blockIdx.x << 6;
    const uint32_t sb = smem_to_u32(smem);
    const int lr = lane >> 2, lq = lane & 3;
    const int qrow0 = b * 1024 + q0 + wid * 16 + lr;   // global row = b*Q + q

    // ---- load Q tile 64x128 hi/lo ----
    {
        int seg = tid;
        #pragma unroll
        for (int i = 0; i < 8; ++i, seg += 128) {
            int r = seg >> 4, s = seg & 15;
            uint32_t d = sb + FL_SQH + r * FL_QP + s * 16;
            long long g = ((long long)(b * 1024 + q0 + r) << 10) + h * 128 + s * 8;
            cp16(d, qh + g);
            cp16(d + (FL_SQL - FL_SQH), ql + g);
        }
        cp_commit(); cp_wait0();
    }
    __syncthreads();

    const uint32_t aoff  = ((lane & 7) + ((lane >> 3) & 1) * 8) * FL_QP + ((lane >> 4) & 1) * 16;
    const uint32_t boffK = ((lane & 7) + ((lane >> 4) & 1) * 8) * FL_QP + ((lane >> 3) & 1) * 16;
    const uint32_t boffV = ((lane & 7) + ((lane >> 4) & 1) * 8) * FL_VP + ((lane >> 3) & 1) * 16;

    // Q fragments in registers (8 k-steps x 4 regs, hi+lo)
    uint32_t qfh[8][4], qfl[8][4];
    #pragma unroll
    for (int ks = 0; ks < 8; ++ks) {
        uint32_t ad = sb + FL_SQH + (wid * 16) * FL_QP + ks * 32 + aoff;
        ldsm_x4(qfh[ks], ad);
        ldsm_x4(qfl[ks], ad + (FL_SQL - FL_SQH));
    }

    float accO[16][4];
    #pragma unroll
    for (int i = 0; i < 16; ++i)
        #pragma unroll
        for (int j = 0; j < 4; ++j) accO[i][j] = 0.f;
    float mrow[2] = {-3.0e38f, -3.0e38f};
    float lrow[2] = {0.f, 0.f};
    const float inv = 0.08838834764831845f;   // 1/sqrt(128)
    const float L2E = 1.4426950408889634f;

    for (int tc = 0; tc < 16; ++tc) {
        const int t0 = tc << 6;

        // bias tile for this thread's S elements (16 pairs), plus liveness vote
        uint32_t braw[16];
        int alive = 0;
        #pragma unroll
        for (int nf = 0; nf < 8; ++nf) {
            const int t = t0 + nf * 8 + lq * 2;
            #pragma unroll
            for (int i2 = 0; i2 < 2; ++i2) {
                uint32_t v = *(const uint32_t*)(bias + ((long long)(qrow0 + 8 * i2) << 10) + t);
                braw[nf * 2 + i2] = v;
                __nv_bfloat162 bb = *(__nv_bfloat162*)&v;
                if (__bfloat162float(bb.x) > -1.0e4f || __bfloat162float(bb.y) > -1.0e4f)
                    alive = 1;
            }
        }
        if (!__syncthreads_or(alive)) continue;   // fully-masked chunk

        // ---- load K chunk [64 t][128 d], V chunk [128 d][64 t] hi/lo ----
        int seg = tid;
        #pragma unroll
        for (int i = 0; i < 8; ++i, seg += 128) {
            int r = seg >> 4, s = seg & 15;
            uint32_t d = sb + FL_SKH + r * FL_QP + s * 16;
            long long g = ((long long)(b * 1024 + t0 + r) << 10) + h * 128 + s * 8;
            cp16(d, kh + g);
            cp16(d + (FL_SKL - FL_SKH), kl + g);
        }
        seg = tid;
        #pragma unroll
        for (int i = 0; i < 8; ++i, seg += 128) {
            int r = seg >> 3, s = seg & 7;
            uint32_t d = sb + FL_SVH + r * FL_VP + s * 16;
            long long g = ((long long)(h * 128 + r) << 12) + b * 1024 + t0 + s * 8;
            cp16(d, vth + g);
            cp16(d + (FL_SVL - FL_SVH), vtl + g);
        }
        cp_commit(); cp_wait0();
        __syncthreads();

        // ---- S = Q K^T (bf16x3) ----
        float accS[8][4];
        #pragma unroll
        for (int i = 0; i < 8; ++i)
            #pragma unroll
            for (int j = 0; j < 4; ++j) accS[i][j] = 0.f;
        #pragma unroll
        for (int ks = 0; ks < 8; ++ks) {
            #pragma unroll
            for (int nt = 0; nt < 4; ++nt) {
                uint32_t bh4[4], bl4[4];
                uint32_t bd = sb + FL_SKH + (nt * 16) * FL_QP + ks * 32 + boffK;
                ldsm_x4(bh4, bd);
                ldsm_x4(bl4, bd + (FL_SKL - FL_SKH));
                mma16816(accS[2 * nt],     qfh[ks], &bh4[0]);
                mma16816(accS[2 * nt + 1], qfh[ks], &bh4[2]);
                mma16816(accS[2 * nt],     qfh[ks], &bl4[0]);
                mma16816(accS[2 * nt + 1], qfh[ks], &bl4[2]);
                mma16816(accS[2 * nt],     qfl[ks], &bh4[0]);
                mma16816(accS[2 * nt + 1], qfl[ks], &bh4[2]);
            }
        }

        // ---- scale + bias, online softmax ----
        float pm[2] = {-3.0e38f, -3.0e38f};
        #pragma unroll
        for (int nf = 0; nf < 8; ++nf) {
            #pragma unroll
            for (int i2 = 0; i2 < 2; ++i2) {
                __nv_bfloat162 bb = *(__nv_bfloat162*)&braw[nf * 2 + i2];
                float s0 = accS[nf][i2 * 2 + 0] * inv + __bfloat162float(bb.x);
                float s1 = accS[nf][i2 * 2 + 1] * inv + __bfloat162float(bb.y);
                accS[nf][i2 * 2 + 0] = s0;
                accS[nf][i2 * 2 + 1] = s1;
                pm[i2] = fmaxf(pm[i2], fmaxf(s0, s1));
            }
        }
        #pragma unroll
        for (int i2 = 0; i2 < 2; ++i2) {
            pm[i2] = fmaxf(pm[i2], __shfl_xor_sync(0xffffffffu, pm[i2], 1));
            pm[i2] = fmaxf(pm[i2], __shfl_xor_sync(0xffffffffu, pm[i2], 2));
            float mnew = fmaxf(mrow[i2], pm[i2]);
            float sc = exp2f((mrow[i2] - mnew) * L2E);
            mrow[i2] = mnew;
            lrow[i2] *= sc;
            #pragma unroll
            for (int nf = 0; nf < 16; ++nf) {
                accO[nf][i2 * 2 + 0] *= sc;
                accO[nf][i2 * 2 + 1] *= sc;
            }
        }
        float psum[2] = {0.f, 0.f};
        #pragma unroll
        for (int nf = 0; nf < 8; ++nf) {
            #pragma unroll
            for (int i2 = 0; i2 < 2; ++i2) {
                float p0 = exp2f((accS[nf][i2 * 2 + 0] - mrow[i2]) * L2E);
                float p1 = exp2f((accS[nf][i2 * 2 + 1] - mrow[i2]) * L2E);
                accS[nf][i2 * 2 + 0] = p0;
                accS[nf][i2 * 2 + 1] = p1;
                psum[i2] += p0 + p1;
            }
        }
        #pragma unroll
        for (int i2 = 0; i2 < 2; ++i2) {
            psum[i2] += __shfl_xor_sync(0xffffffffu, psum[i2], 1);
            psum[i2] += __shfl_xor_sync(0xffffffffu, psum[i2], 2);
            lrow[i2] += psum[i2];
        }

        // ---- O += P V (bf16x3), P fragments from S accumulators ----
        #pragma unroll
        for (int kk = 0; kk < 4; ++kk) {
            uint32_t pah[4], pal[4];
            #pragma unroll
            for (int half = 0; half < 2; ++half) {      // k low/high 8
                const float v0 = accS[2 * kk + half][0], v1 = accS[2 * kk + half][1];
                const float v2 = accS[2 * kk + half][2], v3 = accS[2 * kk + half][3];
                pah[0 + half * 2] = pack_bf162(v0, v1);
                pah[1 + half * 2] = pack_bf162(v2, v3);
                __nv_bfloat162 h01 = *(__nv_bfloat162*)&pah[0 + half * 2];
                __nv_bfloat162 h23 = *(__nv_bfloat162*)&pah[1 + half * 2];
                pal[0 + half * 2] = pack_bf162(v0 - __bfloat162float(h01.x),
                                               v1 - __bfloat162float(h01.y));
                pal[1 + half * 2] = pack_bf162(v2 - __bfloat162float(h23.x),
                                               v3 - __bfloat162float(h23.y));
            }
            #pragma unroll
            for (int np = 0; np < 8; ++np) {
                uint32_t vh4[4], vl4[4];
                uint32_t bd = sb + FL_SVH + (np * 16) * FL_VP + kk * 32 + boffV;
                ldsm_x4(vh4, bd);
                ldsm_x4(vl4, bd + (FL_SVL - FL_SVH));
                mma16816(accO[2 * np],     pah, &vh4[0]);
                mma16816(accO[2 * np + 1], pah, &vh4[2]);
                mma16816(accO[2 * np],     pah, &vl4[0]);
                mma16816(accO[2 * np + 1], pah, &vl4[2]);
                mma16816(accO[2 * np],     pal, &vh4[0]);
                mma16816(accO[2 * np + 1], pal, &vh4[2]);
            }
        }
        __syncthreads();   // smem reads done before next chunk's loads
    }

    // ---- epilogue: O /= l, write split bf16 ----
    float rp[2];
    rp[0] = 1.f / lrow[0];
    rp[1] = 1.f / lrow[1];
    #pragma unroll
    for (int nf = 0; nf < 16; ++nf) {
        #pragma unroll
        for (int i2 = 0; i2 < 2; ++i2) {
            float v0 = accO[nf][i2 * 2 + 0] * rp[i2];
            float v1 = accO[nf][i2 * 2 + 1] * rp[i2];
            long long o = ((long long)(qrow0 + 8 * i2) << 10) + h * 128 + nf * 8 + lq * 2;
            __nv_bfloat162 hh, ll;
            hh.x = __float2bfloat16(v0);
            hh.y = __float2bfloat16(v1);
            ll.x = __float2bfloat16(v0 - __bfloat162float(hh.x));
            ll.y = __float2bfloat16(v1 - __bfloat162float(hh.y));
            *(__nv_bfloat162*)(ph + o) = hh;
            *(__nv_bfloat162*)(pl + o) = ll;
        }
    }
}

// ===========================================================================
// bf16x3 mma.sync GEMM (dense projections / FFN):
//   C[Mrows x N] = A[Mrows x K] * B[N x K]^T  (both split hi/lo bf16)
// CTA tile 128x128, BK=32, 8 warps, cp.async double buffer.
// EPI: 0 none | 1 resid+rowmask | 2 bias+relu | 3 bias+resid+rowmask
// OUT: 0 fp32 C | 1 bf16 hi/lo pair (Ch, Cl)
// ===========================================================================
#define PITCH_B 80
#define TILE_B  (128 * PITCH_B)
#define STAGE_B (4 * TILE_B)
#define MG_SMEM (2 * STAGE_B)

__device__ __forceinline__ void mg_load(
    uint32_t sb, const __nv_bfloat16* __restrict__ Ah, const __nv_bfloat16* __restrict__ Al,
    const __nv_bfloat16* __restrict__ Bh, const __nv_bfloat16* __restrict__ Bl,
    int tid, int m0, int n0, int lda, int ldb, int koff)
{
    int seg = tid;
    #pragma unroll
    for (int i = 0; i < 2; ++i, seg += 256) {
        int r = seg >> 2, s = seg & 3;
        uint32_t d = sb + r * PITCH_B + s * 16;
        const long long g = (long long)(m0 + r) * lda + koff + s * 8;
        cp16(d,          Ah + g);
        cp16(d + TILE_B, Al + g);
    }
    seg = tid;
    #pragma unroll
    for (int i = 0; i < 2; ++i, seg += 256) {
        int r = seg >> 2, s = seg & 3;
        uint32_t d = sb + 2 * TILE_B + r * PITCH_B + s * 16;
        const long long g = (long long)(n0 + r) * ldb + koff + s * 8;
        cp16(d,          Bh + g);
        cp16(d + TILE_B, Bl + g);
    }
    cp_commit();
}

template <int EPI, int OUT>
__global__ void __launch_bounds__(256)
mgemm_k(const __nv_bfloat16* __restrict__ Ah, const __nv_bfloat16* __restrict__ Al, int lda,
        const __nv_bfloat16* __restrict__ Bh, const __nv_bfloat16* __restrict__ Bl, int ldb,
        float* Cf, __nv_bfloat16* Ch, __nv_bfloat16* Cl, int ldc,
        const float* __restrict__ resid, const float* __restrict__ bias,
        const float* __restrict__ rowmask, int Kdim)
{
    extern __shared__ __align__(128) char smem[];
    const int tid = threadIdx.x, wid = tid >> 5, lane = tid & 31;
    const int m0 = blockIdx.y << 7, n0 = blockIdx.x << 7;
    const int wm = (wid >> 1) << 5;
    const int wn = (wid & 1) << 6;
    const uint32_t sb0 = smem_to_u32(smem);

    const uint32_t aoff = ((lane & 7) + ((lane >> 3) & 1) * 8) * PITCH_B + ((lane >> 4) & 1) * 16;
    const uint32_t boff = ((lane & 7) + ((lane >> 4) & 1) * 8) * PITCH_B + ((lane >> 3) & 1) * 16;

    float acc[2][8][4];
    #pragma unroll
    for (int i = 0; i < 2; ++i)
        #pragma unroll
        for (int j = 0; j < 8; ++j)
            #pragma unroll
            for (int k = 0; k < 4; ++k) acc[i][j][k] = 0.f;

    const int NC = Kdim >> 5;
    mg_load(sb0, Ah, Al, Bh, Bl, tid, m0, n0, lda, ldb, 0);

    for (int kt = 0; kt < NC; ++kt) {
        if (kt + 1 < NC) {
            mg_load(sb0 + (uint32_t)((kt + 1) & 1) * STAGE_B,
                    Ah, Al, Bh, Bl, tid, m0, n0, lda, ldb, (kt + 1) << 5);
            cp_wait1();
        } else {
            cp_wait0();
        }
        __syncthreads();

        const uint32_t sA = sb0 + (uint32_t)(kt & 1) * STAGE_B;
        const uint32_t sB = sA + 2 * TILE_B;
        #pragma unroll
        for (int k0 = 0; k0 < 2; ++k0) {
            uint32_t a_hi[2][4], a_lo[2][4], b_hi[4][4], b_lo[4][4];
            #pragma unroll
            for (int mf = 0; mf < 2; ++mf) {
                uint32_t ad = sA + (wm + mf * 16) * PITCH_B + k0 * 32 + aoff;
                ldsm_x4(a_hi[mf], ad);
                ldsm_x4(a_lo[mf], ad + TILE_B);
            }
            #pragma unroll
            for (int np = 0; np < 4; ++np) {
                uint32_t bd = sB + (wn + np * 16) * PITCH_B + k0 * 32 + boff;
                ldsm_x4(b_hi[np], bd);
                ldsm_x4(b_lo[np], bd + TILE_B);
            }
            #pragma unroll
            for (int mf = 0; mf < 2; ++mf)
                #pragma unroll
                for (int np = 0; np < 4; ++np) {
                    mma16816(acc[mf][2 * np],     a_hi[mf], &b_hi[np][0]);
                    mma16816(acc[mf][2 * np + 1], a_hi[mf], &b_hi[np][2]);
                    mma16816(acc[mf][2 * np],     a_hi[mf], &b_lo[np][0]);
                    mma16816(acc[mf][2 * np + 1], a_hi[mf], &b_lo[np][2]);
                    mma16816(acc[mf][2 * np],     a_lo[mf], &b_hi[np][0]);
                    mma16816(acc[mf][2 * np + 1], a_lo[mf], &b_hi[np][2]);
                }
        }
        __syncthreads();
    }

    const int lr = lane >> 2, lc2 = (lane & 3) << 1;
    #pragma unroll
    for (int mf = 0; mf < 2; ++mf) {
        #pragma unroll
        for (int h2 = 0; h2 < 2; ++h2) {
            const long long r = m0 + wm + mf * 16 + h2 * 8 + lr;
            float mfac = 1.f;
            if (EPI == 1 || EPI == 3) mfac = 1.f - rowmask[r];
            #pragma unroll
            for (int nf = 0; nf < 8; ++nf) {
                float v0 = acc[mf][nf][h2 * 2 + 0];
                float v1 = acc[mf][nf][h2 * 2 + 1];
                const long long c = n0 + wn + nf * 8 + lc2;
                if (EPI >= 2) { v0 += bias[c]; v1 += bias[c + 1]; }
                if (EPI == 2) { v0 = fmaxf(v0, 0.f); v1 = fmaxf(v1, 0.f); }
                if (EPI == 1 || EPI == 3) {
                    float2 rs = *(const float2*)(resid + r * ldc + c);
                    v0 = rs.x + v0 * mfac;
                    v1 = rs.y + v1 * mfac;
                }
                if (OUT == 0) {
                    float2 o; o.x = v0; o.y = v1;
                    *(float2*)(Cf + r * ldc + c) = o;
                } else {
                    __nv_bfloat16 h0 = __float2bfloat16(v0), h1 = __float2bfloat16(v1);
                    __nv_bfloat162 hh, ll;
                    hh.x = h0; hh.y = h1;
                    ll.x = __float2bfloat16(v0 - __bfloat162float(h0));
                    ll.y = __float2bfloat16(v1 - __bfloat162float(h1));
                    *(__nv_bfloat162*)(Ch + r * ldc + c) = hh;
                    *(__nv_bfloat162*)(Cl + r * ldc + c) = ll;
                }
            }
        }
    }
}

// ===========================================================================
// Host orchestration
// ===========================================================================
extern "C" void kernel_launch(void* const* d_in, const int* in_sizes, int n_in,
                              void* d_out, int out_size)
{
    (void)in_sizes; (void)n_in; (void)out_size;

    const float* enc_out = (const float*)d_in[0];
    const float* x       = (const float*)d_in[1];
    const float* pmask   = (const float*)d_in[2];
    const float* qtself  = (const float*)d_in[3];
    const float* qtcross = (const float*)d_in[4];
    const float* swq = (const float*)d_in[5];
    const float* swk = (const float*)d_in[6];
    const float* swv = (const float*)d_in[7];
    const float* swo = (const float*)d_in[8];
    const float* cwq = (const float*)d_in[9];
    const float* cwk = (const float*)d_in[10];
    const float* cwv = (const float*)d_in[11];
    const float* cwo = (const float*)d_in[12];
    const float* w1  = (const float*)d_in[13];
    const float* b1  = (const float*)d_in[14];
    const float* w2  = (const float*)d_in[15];
    const float* b2  = (const float*)d_in[16];
    const float* ln1g = (const float*)d_in[17];
    const float* ln1b = (const float*)d_in[18];
    const float* ln2g = (const float*)d_in[19];
    const float* ln2b = (const float*)d_in[20];
    const float* ln3g = (const float*)d_in[21];
    const float* ln3b = (const float*)d_in[22];

    float* hb;
    cudaGetSymbolAddress((void**)&hb, g_h);

    __nv_bfloat16 *wqs_h, *wqs_l, *wks_h, *wks_l, *wvs_h, *wvs_l;
    __nv_bfloat16 *wqc_h, *wqc_l, *wkc_h, *wkc_l, *wvc_h, *wvc_l;
    __nv_bfloat16 *wos_h, *wos_l, *woc_h, *woc_l, *w1h, *w1l, *w2h, *w2l;
    __nv_bfloat16 *nh, *nl, *qh, *ql, *kh, *kl, *vth, *vtl, *ph, *pl;
    __nv_bfloat16 *eh, *el, *sh, *sl, *bs, *bc;
    cudaGetSymbolAddress((void**)&wqs_h, g_wqs_h); cudaGetSymbolAddress((void**)&wqs_l, g_wqs_l);
    cudaGetSymbolAddress((void**)&wks_h, g_wks_h); cudaGetSymbolAddress((void**)&wks_l, g_wks_l);
    cudaGetSymbolAddress((void**)&wvs_h, g_wvs_h); cudaGetSymbolAddress((void**)&wvs_l, g_wvs_l);
    cudaGetSymbolAddress((void**)&wqc_h, g_wqc_h); cudaGetSymbolAddress((void**)&wqc_l, g_wqc_l);
    cudaGetSymbolAddress((void**)&wkc_h, g_wkc_h); cudaGetSymbolAddress((void**)&wkc_l, g_wkc_l);
    cudaGetSymbolAddress((void**)&wvc_h, g_wvc_h); cudaGetSymbolAddress((void**)&wvc_l, g_wvc_l);
    cudaGetSymbolAddress((void**)&wos_h, g_wos_h); cudaGetSymbolAddress((void**)&wos_l, g_wos_l);
    cudaGetSymbolAddress((void**)&woc_h, g_woc_h); cudaGetSymbolAddress((void**)&woc_l, g_woc_l);
    cudaGetSymbolAddress((void**)&w1h, g_w1_h);    cudaGetSymbolAddress((void**)&w1l, g_w1_l);
    cudaGetSymbolAddress((void**)&w2h, g_w2_h);    cudaGetSymbolAddress((void**)&w2l, g_w2_l);
    cudaGetSymbolAddress((void**)&nh, g_nh);   cudaGetSymbolAddress((void**)&nl, g_nl);
    cudaGetSymbolAddress((void**)&qh, g_qh);   cudaGetSymbolAddress((void**)&ql, g_ql);
    cudaGetSymbolAddress((void**)&kh, g_kh);   cudaGetSymbolAddress((void**)&kl, g_kl);
    cudaGetSymbolAddress((void**)&vth, g_vth); cudaGetSymbolAddress((void**)&vtl, g_vtl);
    cudaGetSymbolAddress((void**)&ph, g_ph);   cudaGetSymbolAddress((void**)&pl, g_pl);
    cudaGetSymbolAddress((void**)&eh, g_eh);   cudaGetSymbolAddress((void**)&el, g_el);
    cudaGetSymbolAddress((void**)&sh, g_sh);   cudaGetSymbolAddress((void**)&sl, g_sl);
    cudaGetSymbolAddress((void**)&bs, g_bias_s); cudaGetSymbolAddress((void**)&bc, g_bias_c);

    cudaFuncSetAttribute(mgemm_k<0,1>, cudaFuncAttributeMaxDynamicSharedMemorySize, MG_SMEM);
    cudaFuncSetAttribute(mgemm_k<1,0>, cudaFuncAttributeMaxDynamicSharedMemorySize, MG_SMEM);
    cudaFuncSetAttribute(mgemm_k<2,1>, cudaFuncAttributeMaxDynamicSharedMemorySize, MG_SMEM);
    cudaFuncSetAttribute(mgemm_k<3,0>, cudaFuncAttributeMaxDynamicSharedMemorySize, MG_SMEM);
    cudaFuncSetAttribute(flash_k, cudaFuncAttributeMaxDynamicSharedMemorySize, FL_SMEM);

    // --- weight prep: transpose + bf16 split ---
    {
        dim3 gq(K_ / 32, M_ / 32, L_ * H_);
        tsplit_k<<<gq, 256>>>(swq, wqs_h, wqs_l, M_, K_);
        tsplit_k<<<gq, 256>>>(swk, wks_h, wks_l, M_, K_);
        tsplit_k<<<gq, 256>>>(swv, wvs_h, wvs_l, M_, K_);
        tsplit_k<<<gq, 256>>>(cwq, wqc_h, wqc_l, M_, K_);
        tsplit_k<<<gq, 256>>>(cwk, wkc_h, wkc_l, M_, K_);
        tsplit_k<<<gq, 256>>>(cwv, wvc_h, wvc_l, M_, K_);
        dim3 go(M_ / 32, (H_ * V_) / 32, L_);
        tsplit_k<<<go, 256>>>(swo, wos_h, wos_l, H_ * V_, M_);
        tsplit_k<<<go, 256>>>(cwo, woc_h, woc_l, H_ * V_, M_);
        dim3 g1(F_ / 32, M_ / 32, L_);
        tsplit_k<<<g1, 256>>>(w1, w1h, w1l, M_, F_);
        dim3 g2(M_ / 32, F_ / 32, L_);
        tsplit_k<<<g2, 256>>>(w2, w2h, w2l, F_, M_);
    }
    split_k<<<B_ * T_ * M_ / 4 / 256, 256>>>(enc_out, eh, el, B_ * T_ * M_ / 4);

    // --- mask bias arrays (once per pass type) ---
    bias_build_k<<<B_ * Q_ * T_ / 2 / 256, 256>>>(pmask, qtself, bs);
    bias_build_k<<<B_ * Q_ * T_ / 2 / 256, 256>>>(nullptr, qtcross, bc);

    cudaMemcpyAsync(hb, x, (size_t)BQ_ * M_ * sizeof(float), cudaMemcpyDeviceToDevice);

    const dim3 gP (M_ / 128, BQ_ / 128);     // projections / FFN2
    const dim3 gVT(BQ_ / 128, M_ / 128);     // vT
    const dim3 gF1(F_ / 128, BQ_ / 128);     // FFN1
    const dim3 gFL(Q_ / 64, B_ * H_);        // flash: 16 qtiles x 32 bh
    const size_t wL  = 1048576;
    const size_t wLF = 4194304;

    for (int l = 0; l < L_; ++l) {
        for (int pass = 0; pass < 2; ++pass) {
            const bool self = (pass == 0);
            const float* lng = self ? ln1g : ln2g;
            const float* lnb = self ? ln1b : ln2b;
            __nv_bfloat16* wq_h = (self ? wqs_h : wqc_h) + l * wL;
            __nv_bfloat16* wq_l = (self ? wqs_l : wqc_l) + l * wL;
            __nv_bfloat16* wk_h = (self ? wks_h : wkc_h) + l * wL;
            __nv_bfloat16* wk_l = (self ? wks_l : wkc_l) + l * wL;
            __nv_bfloat16* wv_h = (self ? wvs_h : wvc_h) + l * wL;
            __nv_bfloat16* wv_l = (self ? wvs_l : wvc_l) + l * wL;
            __nv_bfloat16* wo_h = (self ? wos_h : woc_h) + l * wL;
            __nv_bfloat16* wo_l = (self ? wos_l : woc_l) + l * wL;
            __nv_bfloat16* kv_h = self ? nh : eh;
            __nv_bfloat16* kv_l = self ? nl : el;

            layernorm_split_k<<<BQ_, 256>>>(hb, lng + l * M_, lnb + l * M_, nh, nl);
            // q = n Wq^T
            mgemm_k<0,1><<<gP, 256, MG_SMEM>>>(nh, nl, M_, wq_h, wq_l, M_,
                                               nullptr, qh, ql, M_,
                                               nullptr, nullptr, nullptr, M_);
            // k = kv Wk^T
            mgemm_k<0,1><<<gP, 256, MG_SMEM>>>(kv_h, kv_l, M_, wk_h, wk_l, M_,
                                               nullptr, kh, kl, M_,
                                               nullptr, nullptr, nullptr, M_);
            // vT = Wv kv^T  [1024 (h*d)][4096 (b*t)]
            mgemm_k<0,1><<<gVT, 256, MG_SMEM>>>(wv_h, wv_l, M_, kv_h, kv_l, M_,
                                                nullptr, vth, vtl, BQ_,
                                                nullptr, nullptr, nullptr, M_);
            // fused attention -> pre (split)
            flash_k<<<gFL, 128, FL_SMEM>>>(qh, ql, kh, kl, vth, vtl,
                                           self ? bs : bc, ph, pl);
            // h += (pre Wo^T) * (1 - mask)
            mgemm_k<1,0><<<gP, 256, MG_SMEM>>>(ph, pl, M_, wo_h, wo_l, M_,
                                               hb, nullptr, nullptr, M_,
                                               hb, nullptr, pmask, M_);
        }

        // ---- FFN ----
        layernorm_split_k<<<BQ_, 256>>>(hb, ln3g + l * M_, ln3b + l * M_, nh, nl);
        mgemm_k<2,1><<<gF1, 256, MG_SMEM>>>(nh, nl, M_, w1h + l * wLF, w1l + l * wLF, M_,
                                            nullptr, sh, sl, F_,
                                            nullptr, b1 + l * F_, nullptr, M_);
        mgemm_k<3,0><<<gP, 256, MG_SMEM>>>(sh, sl, F_, w2h + l * wLF, w2l + l * wLF, F_,
                                           hb, nullptr, nullptr, M_,
                                           hb, b2 + l * M_, pmask, F_);
    }

    cudaMemcpyAsync(d_out, hb, (size_t)BQ_ * M_ * sizeof(float),
                    cudaMemcpyDeviceToDevice);
}

// round 6
// speedup vs baseline: 2.6348x; 1.0189x over previous
#include <cuda_runtime.h>
#include <cuda_bf16.h>
#include <cstdint>
#include <cstddef>

// Problem constants
#define L_  6
#define H_  8
#define M_  1024
#define K_  128
#define V_  128
#define F_  4096
#define B_  4
#define Q_  1024
#define T_  1024
#define BQ_ 4096   // B_*Q_

// ===========================================================================
// Low-level helpers (base PTX only — no sm_103a-specific instructions)
// ===========================================================================
__device__ __forceinline__ uint32_t smem_to_u32(const void* p) {
    uint32_t a;
    asm("{ .reg .u64 t; cvta.to.shared.u64 t, %1; cvt.u32.u64 %0, t; }"
        : "=r"(a) : "l"(p));
    return a;
}

__device__ __forceinline__ void cp16(uint32_t dst, const void* src) {
    asm volatile("cp.async.cg.shared.global [%0], [%1], 16;"
                 :: "r"(dst), "l"(__cvta_generic_to_global(src)));
}
__device__ __forceinline__ void cp_commit() { asm volatile("cp.async.commit_group;" ::: "memory"); }
__device__ __forceinline__ void cp_wait0()  { asm volatile("cp.async.wait_group 0;" ::: "memory"); }
__device__ __forceinline__ void cp_wait1()  { asm volatile("cp.async.wait_group 1;" ::: "memory"); }
__device__ __forceinline__ void cp_wait2()  { asm volatile("cp.async.wait_group 2;" ::: "memory"); }

__device__ __forceinline__ void ldsm_x4(uint32_t* r, uint32_t addr) {
    asm volatile("ldmatrix.sync.aligned.m8n8.x4.shared.b16 {%0,%1,%2,%3}, [%4];"
                 : "=r"(r[0]), "=r"(r[1]), "=r"(r[2]), "=r"(r[3]) : "r"(addr));
}

__device__ __forceinline__ void ldsm_x4_t(uint32_t* r, uint32_t addr) {
    asm volatile("ldmatrix.sync.aligned.m8n8.x4.trans.shared.b16 {%0,%1,%2,%3}, [%4];"
                 : "=r"(r[0]), "=r"(r[1]), "=r"(r[2]), "=r"(r[3]) : "r"(addr));
}

__device__ __forceinline__ void mma16816(float* d, const uint32_t* a, const uint32_t* b) {
    asm volatile(
        "mma.sync.aligned.m16n8k16.row.col.f32.bf16.bf16.f32 "
        "{%0,%1,%2,%3}, {%4,%5,%6,%7}, {%8,%9}, {%0,%1,%2,%3};"
        : "+f"(d[0]), "+f"(d[1]), "+f"(d[2]), "+f"(d[3])
        : "r"(a[0]), "r"(a[1]), "r"(a[2]), "r"(a[3]), "r"(b[0]), "r"(b[1]));
}

__device__ __forceinline__ uint32_t pack_bf162(float a, float b) {
    __nv_bfloat162 t;
    t.x = __float2bfloat16(a);
    t.y = __float2bfloat16(b);
    return *(uint32_t*)&t;
}

// ===========================================================================
// Scratch (device globals; no runtime allocation allowed)
// ===========================================================================
__device__ float g_h[(size_t)BQ_ * M_];

// concat qkv weights [l][3072][1024] (rows 0-1023 q, 1024-2047 k, 2048-3071 v)
#define WCAT_SZ ((size_t)L_ * 3072 * 1024)
#define WO_SZ   ((size_t)L_ * 1048576)
#define WFF_SZ  ((size_t)L_ * 4194304)
__device__ __align__(256) __nv_bfloat16 g_wqkvs_h[WCAT_SZ], g_wqkvs_l[WCAT_SZ];
__device__ __align__(256) __nv_bfloat16 g_wqkvc_h[WCAT_SZ], g_wqkvc_l[WCAT_SZ];
__device__ __align__(256) __nv_bfloat16 g_wos_h[WO_SZ], g_wos_l[WO_SZ];
__device__ __align__(256) __nv_bfloat16 g_woc_h[WO_SZ], g_woc_l[WO_SZ];
__device__ __align__(256) __nv_bfloat16 g_w1_h[WFF_SZ], g_w1_l[WFF_SZ];
__device__ __align__(256) __nv_bfloat16 g_w2_h[WFF_SZ], g_w2_l[WFF_SZ];

// bf16 split activations
__device__ __align__(256) __nv_bfloat16 g_nh [(size_t)BQ_ * M_], g_nl [(size_t)BQ_ * M_];
__device__ __align__(256) __nv_bfloat16 g_qkvh[(size_t)BQ_ * 3072], g_qkvl[(size_t)BQ_ * 3072];
__device__ __align__(256) __nv_bfloat16 g_ph [(size_t)BQ_ * M_], g_pl [(size_t)BQ_ * M_];
__device__ __align__(256) __nv_bfloat16 g_eh [(size_t)B_ * T_ * M_], g_el [(size_t)B_ * T_ * M_];
__device__ __align__(256) __nv_bfloat16 g_sh [(size_t)BQ_ * F_], g_sl [(size_t)BQ_ * F_];

// mask bias arrays: [B][Q][T] bf16 = max(tmask,qtmask) * (-1e6/sqrt(128))
__device__ __align__(256) __nv_bfloat16 g_bias_s[(size_t)B_ * Q_ * T_];
__device__ __align__(256) __nv_bfloat16 g_bias_c[(size_t)B_ * Q_ * T_];

// ===========================================================================
// Block reductions (blockDim.x == 256)
// ===========================================================================
__device__ __forceinline__ float block_sum(float v) {
    __shared__ float sh[8];
    #pragma unroll
    for (int o = 16; o > 0; o >>= 1) v += __shfl_xor_sync(0xffffffffu, v, o);
    __syncthreads();
    if ((threadIdx.x & 31) == 0) sh[threadIdx.x >> 5] = v;
    __syncthreads();
    float t = 0.f;
    #pragma unroll
    for (int i = 0; i < 8; ++i) t += sh[i];
    return t;
}

// ===========================================================================
// Batched transpose + bf16 hi/lo split: per z, [R][C] fp32 -> [C][R] bf16x2
// dst base = (z>>zs)*s1 + (z & ((1<<zs)-1))*s2 + s3
// ===========================================================================
__global__ void __launch_bounds__(256)
tsplit_k(const float* __restrict__ src, __nv_bfloat16* __restrict__ hi,
         __nv_bfloat16* __restrict__ lo, int R, int C,
         int zs, long long s1, long long s2, long long s3)
{
    __shared__ float t[32][33];
    const int z = blockIdx.z;
    const long long sbase = (long long)z * R * C;
    const long long dbase = (long long)(z >> zs) * s1 +
                            (long long)(z & ((1 << zs) - 1)) * s2 + s3;
    const int c0 = blockIdx.x << 5, r0 = blockIdx.y << 5;
    const int tx = threadIdx.x & 31, ty = threadIdx.x >> 5;
    #pragma unroll
    for (int i = 0; i < 4; ++i) {
        int r = r0 + ty + i * 8;
        t[ty + i * 8][tx] = src[sbase + (long long)r * C + c0 + tx];
    }
    __syncthreads();
    #pragma unroll
    for (int i = 0; i < 4; ++i) {
        int c = c0 + ty + i * 8;
        float v = t[tx][ty + i * 8];
        __nv_bfloat16 h = __float2bfloat16(v);
        long long o = dbase + (long long)c * R + r0 + tx;
        hi[o] = h;
        lo[o] = __float2bfloat16(v - __bfloat162float(h));
    }
}

// ===========================================================================
// Elementwise bf16 hi/lo split (vectorized by 4)
// ===========================================================================
__global__ void __launch_bounds__(256)
split_k(const float* __restrict__ x, __nv_bfloat16* __restrict__ hi,
        __nv_bfloat16* __restrict__ lo, int n4)
{
    int i = blockIdx.x * 256 + threadIdx.x;
    if (i >= n4) return;
    float4 v = ((const float4*)x)[i];
    __nv_bfloat16 h[4], l[4];
    h[0] = __float2bfloat16(v.x); l[0] = __float2bfloat16(v.x - __bfloat162float(h[0]));
    h[1] = __float2bfloat16(v.y); l[1] = __float2bfloat16(v.y - __bfloat162float(h[1]));
    h[2] = __float2bfloat16(v.z); l[2] = __float2bfloat16(v.z - __bfloat162float(h[2]));
    h[3] = __float2bfloat16(v.w); l[3] = __float2bfloat16(v.w - __bfloat162float(h[3]));
    *(uint2*)(hi + 4 * (size_t)i) = *(uint2*)h;
    *(uint2*)(lo + 4 * (size_t)i) = *(uint2*)l;
}

// ===========================================================================
// Mask bias build: out[b,q,t] = max(tmask[b,t], qtmask[b,q,t]) * (-1e6/sqrt(128))
// ===========================================================================
__global__ void __launch_bounds__(256)
bias_build_k(const float* __restrict__ tmask, const float* __restrict__ qtmask,
             __nv_bfloat16* __restrict__ out)
{
    const long long i2 = ((long long)blockIdx.x * 256 + threadIdx.x) * 2;
    const int t = (int)(i2 & 1023);
    const int b = (int)(i2 >> 20);
    float m0 = qtmask[i2], m1 = qtmask[i2 + 1];
    if (tmask) {
        m0 = fmaxf(m0, tmask[b * 1024 + t]);
        m1 = fmaxf(m1, tmask[b * 1024 + t + 1]);
    }
    const float c = -88388.34765f;   // -1e6 / sqrt(128)
    __nv_bfloat162 o;
    o.x = __float2bfloat16(m0 * c);
    o.y = __float2bfloat16(m1 * c);
    *(__nv_bfloat162*)(out + i2) = o;
}

// ===========================================================================
// LayerNorm over M=1024, emitting bf16 hi/lo split. One block per row.
// ===========================================================================
__global__ void __launch_bounds__(256)
layernorm_split_k(const float* __restrict__ x, const float* __restrict__ g,
                  const float* __restrict__ b,
                  __nv_bfloat16* __restrict__ hi, __nv_bfloat16* __restrict__ lo)
{
    const int row = blockIdx.x;
    const float* xp = x + (size_t)row * M_;
    const int c = threadIdx.x << 2;
    float4 d = *(const float4*)(xp + c);
    float s  = d.x + d.y + d.z + d.w;
    float ss = d.x * d.x + d.y * d.y + d.z * d.z + d.w * d.w;
    s  = block_sum(s);
    ss = block_sum(ss);
    const float mean = s * (1.f / M_);
    const float var  = ss * (1.f / M_) - mean * mean;
    const float inv  = rsqrtf(var + 1e-5f);
    float4 g4 = *(const float4*)(g + c);
    float4 b4 = *(const float4*)(b + c);
    float o[4];
    o[0] = (d.x - mean) * inv * g4.x + b4.x;
    o[1] = (d.y - mean) * inv * g4.y + b4.y;
    o[2] = (d.z - mean) * inv * g4.z + b4.z;
    o[3] = (d.w - mean) * inv * g4.w + b4.w;
    __nv_bfloat16 h[4], l[4];
    #pragma unroll
    for (int i = 0; i < 4; ++i) {
        h[i] = __float2bfloat16(o[i]);
        l[i] = __float2bfloat16(o[i] - __bfloat162float(h[i]));
    }
    *(uint2*)(hi + (size_t)row * M_ + c) = *(uint2*)h;
    *(uint2*)(lo + (size_t)row * M_ + c) = *(uint2*)l;
}

// ===========================================================================
// Fused flash attention (bf16x3, fp32 softmax/accum).
// CTA: 64 q-rows of one (b,h); 4 warps. Q registers; K/V chunks in smem.
// qkv buffer: [b*t][3072] (q: +0, k: +1024, v: +2048 ; within: h*128+d).
// V stored row-major [t][d]; PV B-fragments via ldmatrix.trans.
// Output: ph/pl [b*q][1024] split bf16.
// ===========================================================================
#define FL_QP  272                 // smem pitch bytes (128 bf16 + 16 pad)
#define FL_SQH 0
#define FL_SQL 17408
#define FL_SKH 34816
#define FL_SKL 52224
#define FL_SVH 69632
#define FL_SVL 87040
#define FL_SMEM 104448

__global__ void __launch_bounds__(128)
flash_k(const __nv_bfloat16* __restrict__ qkvh, const __nv_bfloat16* __restrict__ qkvl,
        const __nv_bfloat16* __restrict__ bias,
        __nv_bfloat16* __restrict__ ph, __nv_bfloat16* __restrict__ pl)
{
    extern __shared__ __align__(128) char smem[];
    const int tid = threadIdx.x, wid = tid >> 5, lane = tid & 31;
    const int bh = blockIdx.y, b = bh >> 3, h = bh & 7;
    const int q0 = blockIdx.x << 6;
    const uint32_t sb = smem_to_u32(smem);
    const int lr = lane >> 2, lq = lane & 3;
    const int qrow0 = b * 1024 + q0 + wid * 16 + lr;   // global row = b*Q + q

    // ---- load Q tile 64x128 hi/lo ----
    {
        int seg = tid;
        #pragma unroll
        for (int i = 0; i < 8; ++i, seg += 128) {
            int r = seg >> 4, s = seg & 15;
            uint32_t d = sb + FL_SQH + r * FL_QP + s * 16;
            long long g = (long long)(b * 1024 + q0 + r) * 3072 + h * 128 + s * 8;
            cp16(d, qkvh + g);
            cp16(d + (FL_SQL - FL_SQH), qkvl + g);
        }
        cp_commit(); cp_wait0();
    }
    __syncthreads();

    const uint32_t aoff  = ((lane & 7) + ((lane >> 3) & 1) * 8) * FL_QP + ((lane >> 4) & 1) * 16;
    const uint32_t boffK = ((lane & 7) + ((lane >> 4) & 1) * 8) * FL_QP + ((lane >> 3) & 1) * 16;

    // Q fragments in registers (8 k-steps x 4 regs, hi+lo)
    uint32_t qfh[8][4], qfl[8][4];
    #pragma unroll
    for (int ks = 0; ks < 8; ++ks) {
        uint32_t ad = sb + FL_SQH + (wid * 16) * FL_QP + ks * 32 + aoff;
        ldsm_x4(qfh[ks], ad);
        ldsm_x4(qfl[ks], ad + (FL_SQL - FL_SQH));
    }

    float accO[16][4];
    #pragma unroll
    for (int i = 0; i < 16; ++i)
        #pragma unroll
        for (int j = 0; j < 4; ++j) accO[i][j] = 0.f;
    float mrow[2] = {-3.0e38f, -3.0e38f};
    float lrow[2] = {0.f, 0.f};
    const float inv = 0.08838834764831845f;   // 1/sqrt(128)
    const float L2E = 1.4426950408889634f;

    for (int tc = 0; tc < 16; ++tc) {
        const int t0 = tc << 6;

        // bias tile + liveness vote
        uint32_t braw[16];
        int alive = 0;
        #pragma unroll
        for (int nf = 0; nf < 8; ++nf) {
            const int t = t0 + nf * 8 + lq * 2;
            #pragma unroll
            for (int i2 = 0; i2 < 2; ++i2) {
                uint32_t v = *(const uint32_t*)(bias + ((long long)(qrow0 + 8 * i2) << 10) + t);
                braw[nf * 2 + i2] = v;
                __nv_bfloat162 bb = *(__nv_bfloat162*)&v;
                if (__bfloat162float(bb.x) > -1.0e4f || __bfloat162float(bb.y) > -1.0e4f)
                    alive = 1;
            }
        }
        if (!__syncthreads_or(alive)) continue;   // fully-masked chunk

        // ---- load K chunk [64 t][128 d] and V chunk [64 t][128 d] hi/lo ----
        int seg = tid;
        #pragma unroll
        for (int i = 0; i < 8; ++i, seg += 128) {
            int r = seg >> 4, s = seg & 15;
            long long g = (long long)(b * 1024 + t0 + r) * 3072 + h * 128 + s * 8;
            uint32_t d = sb + FL_SKH + r * FL_QP + s * 16;
            cp16(d, qkvh + g + 1024);
            cp16(d + (FL_SKL - FL_SKH), qkvl + g + 1024);
            uint32_t dv = sb + FL_SVH + r * FL_QP + s * 16;
            cp16(dv, qkvh + g + 2048);
            cp16(dv + (FL_SVL - FL_SVH), qkvl + g + 2048);
        }
        cp_commit(); cp_wait0();
        __syncthreads();

        // ---- S = Q K^T (bf16x3) ----
        float accS[8][4];
        #pragma unroll
        for (int i = 0; i < 8; ++i)
            #pragma unroll
            for (int j = 0; j < 4; ++j) accS[i][j] = 0.f;
        #pragma unroll
        for (int ks = 0; ks < 8; ++ks) {
            #pragma unroll
            for (int nt = 0; nt < 4; ++nt) {
                uint32_t bh4[4], bl4[4];
                uint32_t bd = sb + FL_SKH + (nt * 16) * FL_QP + ks * 32 + boffK;
                ldsm_x4(bh4, bd);
                ldsm_x4(bl4, bd + (FL_SKL - FL_SKH));
                mma16816(accS[2 * nt],     qfh[ks], &bh4[0]);
                mma16816(accS[2 * nt + 1], qfh[ks], &bh4[2]);
                mma16816(accS[2 * nt],     qfh[ks], &bl4[0]);
                mma16816(accS[2 * nt + 1], qfh[ks], &bl4[2]);
                mma16816(accS[2 * nt],     qfl[ks], &bh4[0]);
                mma16816(accS[2 * nt + 1], qfl[ks], &bh4[2]);
            }
        }

        // ---- scale + bias, online softmax ----
        float pm[2] = {-3.0e38f, -3.0e38f};
        #pragma unroll
        for (int nf = 0; nf < 8; ++nf) {
            #pragma unroll
            for (int i2 = 0; i2 < 2; ++i2) {
                __nv_bfloat162 bb = *(__nv_bfloat162*)&braw[nf * 2 + i2];
                float s0 = accS[nf][i2 * 2 + 0] * inv + __bfloat162float(bb.x);
                float s1 = accS[nf][i2 * 2 + 1] * inv + __bfloat162float(bb.y);
                accS[nf][i2 * 2 + 0] = s0;
                accS[nf][i2 * 2 + 1] = s1;
                pm[i2] = fmaxf(pm[i2], fmaxf(s0, s1));
            }
        }
        #pragma unroll
        for (int i2 = 0; i2 < 2; ++i2) {
            pm[i2] = fmaxf(pm[i2], __shfl_xor_sync(0xffffffffu, pm[i2], 1));
            pm[i2] = fmaxf(pm[i2], __shfl_xor_sync(0xffffffffu, pm[i2], 2));
            float mnew = fmaxf(mrow[i2], pm[i2]);
            float sc = exp2f((mrow[i2] - mnew) * L2E);
            mrow[i2] = mnew;
            lrow[i2] *= sc;
            #pragma unroll
            for (int nf = 0; nf < 16; ++nf) {
                accO[nf][i2 * 2 + 0] *= sc;
                accO[nf][i2 * 2 + 1] *= sc;
            }
        }
        float psum[2] = {0.f, 0.f};
        #pragma unroll
        for (int nf = 0; nf < 8; ++nf) {
            #pragma unroll
            for (int i2 = 0; i2 < 2; ++i2) {
                float p0 = exp2f((accS[nf][i2 * 2 + 0] - mrow[i2]) * L2E);
                float p1 = exp2f((accS[nf][i2 * 2 + 1] - mrow[i2]) * L2E);
                accS[nf][i2 * 2 + 0] = p0;
                accS[nf][i2 * 2 + 1] = p1;
                psum[i2] += p0 + p1;
            }
        }
        #pragma unroll
        for (int i2 = 0; i2 < 2; ++i2) {
            psum[i2] += __shfl_xor_sync(0xffffffffu, psum[i2], 1);
            psum[i2] += __shfl_xor_sync(0xffffffffu, psum[i2], 2);
            lrow[i2] += psum[i2];
        }

        // ---- O += P V (bf16x3); V row-major, B-fragments via ldmatrix.trans ----
        #pragma unroll
        for (int kk = 0; kk < 4; ++kk) {
            uint32_t pah[4], pal[4];
            #pragma unroll
            for (int half = 0; half < 2; ++half) {
                const float v0 = accS[2 * kk + half][0], v1 = accS[2 * kk + half][1];
                const float v2 = accS[2 * kk + half][2], v3 = accS[2 * kk + half][3];
                pah[0 + half * 2] = pack_bf162(v0, v1);
                pah[1 + half * 2] = pack_bf162(v2, v3);
                __nv_bfloat162 h01 = *(__nv_bfloat162*)&pah[0 + half * 2];
                __nv_bfloat162 h23 = *(__nv_bfloat162*)&pah[1 + half * 2];
                pal[0 + half * 2] = pack_bf162(v0 - __bfloat162float(h01.x),
                                               v1 - __bfloat162float(h01.y));
                pal[1 + half * 2] = pack_bf162(v2 - __bfloat162float(h23.x),
                                               v3 - __bfloat162float(h23.y));
            }
            #pragma unroll
            for (int np = 0; np < 8; ++np) {
                uint32_t vh4[4], vl4[4];
                uint32_t bd = sb + FL_SVH + (kk * 16) * FL_QP + np * 32 + aoff;
                ldsm_x4_t(vh4, bd);
                ldsm_x4_t(vl4, bd + (FL_SVL - FL_SVH));
                mma16816(accO[2 * np],     pah, &vh4[0]);
                mma16816(accO[2 * np + 1], pah, &vh4[2]);
                mma16816(accO[2 * np],     pah, &vl4[0]);
                mma16816(accO[2 * np + 1], pah, &vl4[2]);
                mma16816(accO[2 * np],     pal, &vh4[0]);
                mma16816(accO[2 * np + 1], pal, &vh4[2]);
            }
        }
        __syncthreads();   // smem reads done before next chunk's loads
    }

    // ---- epilogue: O /= l, write split bf16 ----
    float rp[2];
    rp[0] = 1.f / lrow[0];
    rp[1] = 1.f / lrow[1];
    #pragma unroll
    for (int nf = 0; nf < 16; ++nf) {
        #pragma unroll
        for (int i2 = 0; i2 < 2; ++i2) {
            float v0 = accO[nf][i2 * 2 + 0] * rp[i2];
            float v1 = accO[nf][i2 * 2 + 1] * rp[i2];
            long long o = ((long long)(qrow0 + 8 * i2) << 10) + h * 128 + nf * 8 + lq * 2;
            __nv_bfloat162 hh, ll;
            hh.x = __float2bfloat16(v0);
            hh.y = __float2bfloat16(v1);
            ll.x = __float2bfloat16(v0 - __bfloat162float(hh.x));
            ll.y = __float2bfloat16(v1 - __bfloat162float(hh.y));
            *(__nv_bfloat162*)(ph + o) = hh;
            *(__nv_bfloat162*)(pl + o) = ll;
        }
    }
}

// ===========================================================================
// bf16x3 mma.sync GEMM (dense): C[M x N] = A[M x K] * B[N x K]^T
// CTA tile 128x128, BK=32, 8 warps, 4-stage cp.async pipeline,
// ONE __syncthreads per chunk.
// EPI: 0 none | 1 resid+rowmask | 2 bias+relu | 3 bias+resid+rowmask
// OUT: 0 fp32 C | 1 bf16 hi/lo pair (Ch, Cl)
// ===========================================================================
#define PITCH_B 80
#define TILE_B  (128 * PITCH_B)
#define STAGE_B (4 * TILE_B)       // 40960
#define MG_SMEM (4 * STAGE_B)      // 163840

__device__ __forceinline__ void mg_load(
    uint32_t sb, const __nv_bfloat16* __restrict__ Ah, const __nv_bfloat16* __restrict__ Al,
    const __nv_bfloat16* __restrict__ Bh, const __nv_bfloat16* __restrict__ Bl,
    int tid, int m0, int n0, int lda, int ldb, int koff)
{
    int seg = tid;
    #pragma unroll
    for (int i = 0; i < 2; ++i, seg += 256) {
        int r = seg >> 2, s = seg & 3;
        uint32_t d = sb + r * PITCH_B + s * 16;
        const long long g = (long long)(m0 + r) * lda + koff + s * 8;
        cp16(d,          Ah + g);
        cp16(d + TILE_B, Al + g);
    }
    seg = tid;
    #pragma unroll
    for (int i = 0; i < 2; ++i, seg += 256) {
        int r = seg >> 2, s = seg & 3;
        uint32_t d = sb + 2 * TILE_B + r * PITCH_B + s * 16;
        const long long g = (long long)(n0 + r) * ldb + koff + s * 8;
        cp16(d,          Bh + g);
        cp16(d + TILE_B, Bl + g);
    }
    cp_commit();
}

template <int EPI, int OUT>
__global__ void __launch_bounds__(256)
mgemm_k(const __nv_bfloat16* __restrict__ Ah, const __nv_bfloat16* __restrict__ Al, int lda,
        const __nv_bfloat16* __restrict__ Bh, const __nv_bfloat16* __restrict__ Bl, int ldb,
        float* Cf, __nv_bfloat16* Ch, __nv_bfloat16* Cl, int ldc,
        const float* __restrict__ resid, int ldr,
        const float* __restrict__ bias,
        const float* __restrict__ rowmask, int Kdim)
{
    extern __shared__ __align__(128) char smem[];
    const int tid = threadIdx.x, wid = tid >> 5, lane = tid & 31;
    const int m0 = blockIdx.y << 7, n0 = blockIdx.x << 7;
    const int wm = (wid >> 1) << 5;
    const int wn = (wid & 1) << 6;
    const uint32_t sb0 = smem_to_u32(smem);

    const uint32_t aoff = ((lane & 7) + ((lane >> 3) & 1) * 8) * PITCH_B + ((lane >> 4) & 1) * 16;
    const uint32_t boff = ((lane & 7) + ((lane >> 4) & 1) * 8) * PITCH_B + ((lane >> 3) & 1) * 16;

    float acc[2][8][4];
    #pragma unroll
    for (int i = 0; i < 2; ++i)
        #pragma unroll
        for (int j = 0; j < 8; ++j)
            #pragma unroll
            for (int k = 0; k < 4; ++k) acc[i][j][k] = 0.f;

    const int NC = Kdim >> 5;   // >= 32 always here
    mg_load(sb0,               Ah, Al, Bh, Bl, tid, m0, n0, lda, ldb, 0);
    mg_load(sb0 + STAGE_B,     Ah, Al, Bh, Bl, tid, m0, n0, lda, ldb, 32);
    mg_load(sb0 + 2 * STAGE_B, Ah, Al, Bh, Bl, tid, m0, n0, lda, ldb, 64);

    for (int kt = 0; kt < NC; ++kt) {
        if (kt + 2 < NC)      cp_wait2();
        else if (kt + 1 < NC) cp_wait1();
        else                  cp_wait0();
        __syncthreads();
        if (kt + 3 < NC)
            mg_load(sb0 + (uint32_t)((kt + 3) & 3) * STAGE_B,
                    Ah, Al, Bh, Bl, tid, m0, n0, lda, ldb, (kt + 3) << 5);

        const uint32_t sA = sb0 + (uint32_t)(kt & 3) * STAGE_B;
        const uint32_t sB = sA + 2 * TILE_B;
        #pragma unroll
        for (int k0 = 0; k0 < 2; ++k0) {
            uint32_t a_hi[2][4], a_lo[2][4], b_hi[4][4], b_lo[4][4];
            #pragma unroll
            for (int mf = 0; mf < 2; ++mf) {
                uint32_t ad = sA + (wm + mf * 16) * PITCH_B + k0 * 32 + aoff;
                ldsm_x4(a_hi[mf], ad);
                ldsm_x4(a_lo[mf], ad + TILE_B);
            }
            #pragma unroll
            for (int np = 0; np < 4; ++np) {
                uint32_t bd = sB + (wn + np * 16) * PITCH_B + k0 * 32 + boff;
                ldsm_x4(b_hi[np], bd);
                ldsm_x4(b_lo[np], bd + TILE_B);
            }
            #pragma unroll
            for (int mf = 0; mf < 2; ++mf)
                #pragma unroll
                for (int np = 0; np < 4; ++np) {
                    mma16816(acc[mf][2 * np],     a_hi[mf], &b_hi[np][0]);
                    mma16816(acc[mf][2 * np + 1], a_hi[mf], &b_hi[np][2]);
                    mma16816(acc[mf][2 * np],     a_hi[mf], &b_lo[np][0]);
                    mma16816(acc[mf][2 * np + 1], a_hi[mf], &b_lo[np][2]);
                    mma16816(acc[mf][2 * np],     a_lo[mf], &b_hi[np][0]);
                    mma16816(acc[mf][2 * np + 1], a_lo[mf], &b_hi[np][2]);
                }
        }
    }

    const int lr = lane >> 2, lc2 = (lane & 3) << 1;
    #pragma unroll
    for (int mf = 0; mf < 2; ++mf) {
        #pragma unroll
        for (int h2 = 0; h2 < 2; ++h2) {
            const long long r = m0 + wm + mf * 16 + h2 * 8 + lr;
            float mfac = 1.f;
            if (EPI == 1 || EPI == 3) mfac = 1.f - rowmask[r];
            #pragma unroll
            for (int nf = 0; nf < 8; ++nf) {
                float v0 = acc[mf][nf][h2 * 2 + 0];
                float v1 = acc[mf][nf][h2 * 2 + 1];
                const long long c = n0 + wn + nf * 8 + lc2;
                if (EPI >= 2) { v0 += bias[c]; v1 += bias[c + 1]; }
                if (EPI == 2) { v0 = fmaxf(v0, 0.f); v1 = fmaxf(v1, 0.f); }
                if (EPI == 1 || EPI == 3) {
                    float2 rs = *(const float2*)(resid + r * ldr + c);
                    v0 = rs.x + v0 * mfac;
                    v1 = rs.y + v1 * mfac;
                }
                if (OUT == 0) {
                    float2 o; o.x = v0; o.y = v1;
                    *(float2*)(Cf + r * ldc + c) = o;
                } else {
                    __nv_bfloat16 h0 = __float2bfloat16(v0), h1 = __float2bfloat16(v1);
                    __nv_bfloat162 hh, ll;
                    hh.x = h0; hh.y = h1;
                    ll.x = __float2bfloat16(v0 - __bfloat162float(h0));
                    ll.y = __float2bfloat16(v1 - __bfloat162float(h1));
                    *(__nv_bfloat162*)(Ch + r * ldc + c) = hh;
                    *(__nv_bfloat162*)(Cl + r * ldc + c) = ll;
                }
            }
        }
    }
}

// ===========================================================================
// Host orchestration
// ===========================================================================
extern "C" void kernel_launch(void* const* d_in, const int* in_sizes, int n_in,
                              void* d_out, int out_size)
{
    (void)in_sizes; (void)n_in; (void)out_size;

    const float* enc_out = (const float*)d_in[0];
    const float* x       = (const float*)d_in[1];
    const float* pmask   = (const float*)d_in[2];
    const float* qtself  = (const float*)d_in[3];
    const float* qtcross = (const float*)d_in[4];
    const float* swq = (const float*)d_in[5];
    const float* swk = (const float*)d_in[6];
    const float* swv = (const float*)d_in[7];
    const float* swo = (const float*)d_in[8];
    const float* cwq = (const float*)d_in[9];
    const float* cwk = (const float*)d_in[10];
    const float* cwv = (const float*)d_in[11];
    const float* cwo = (const float*)d_in[12];
    const float* w1  = (const float*)d_in[13];
    const float* b1  = (const float*)d_in[14];
    const float* w2  = (const float*)d_in[15];
    const float* b2  = (const float*)d_in[16];
    const float* ln1g = (const float*)d_in[17];
    const float* ln1b = (const float*)d_in[18];
    const float* ln2g = (const float*)d_in[19];
    const float* ln2b = (const float*)d_in[20];
    const float* ln3g = (const float*)d_in[21];
    const float* ln3b = (const float*)d_in[22];

    float* hb;
    cudaGetSymbolAddress((void**)&hb, g_h);

    __nv_bfloat16 *wqkvs_h, *wqkvs_l, *wqkvc_h, *wqkvc_l;
    __nv_bfloat16 *wos_h, *wos_l, *woc_h, *woc_l, *w1h, *w1l, *w2h, *w2l;
    __nv_bfloat16 *nh, *nl, *qkvh, *qkvl, *ph, *pl, *eh, *el, *sh, *sl, *bs, *bc;
    cudaGetSymbolAddress((void**)&wqkvs_h, g_wqkvs_h);
    cudaGetSymbolAddress((void**)&wqkvs_l, g_wqkvs_l);
    cudaGetSymbolAddress((void**)&wqkvc_h, g_wqkvc_h);
    cudaGetSymbolAddress((void**)&wqkvc_l, g_wqkvc_l);
    cudaGetSymbolAddress((void**)&wos_h, g_wos_h); cudaGetSymbolAddress((void**)&wos_l, g_wos_l);
    cudaGetSymbolAddress((void**)&woc_h, g_woc_h); cudaGetSymbolAddress((void**)&woc_l, g_woc_l);
    cudaGetSymbolAddress((void**)&w1h, g_w1_h);    cudaGetSymbolAddress((void**)&w1l, g_w1_l);
    cudaGetSymbolAddress((void**)&w2h, g_w2_h);    cudaGetSymbolAddress((void**)&w2l, g_w2_l);
    cudaGetSymbolAddress((void**)&nh, g_nh);     cudaGetSymbolAddress((void**)&nl, g_nl);
    cudaGetSymbolAddress((void**)&qkvh, g_qkvh); cudaGetSymbolAddress((void**)&qkvl, g_qkvl);
    cudaGetSymbolAddress((void**)&ph, g_ph);     cudaGetSymbolAddress((void**)&pl, g_pl);
    cudaGetSymbolAddress((void**)&eh, g_eh);     cudaGetSymbolAddress((void**)&el, g_el);
    cudaGetSymbolAddress((void**)&sh, g_sh);     cudaGetSymbolAddress((void**)&sl, g_sl);
    cudaGetSymbolAddress((void**)&bs, g_bias_s); cudaGetSymbolAddress((void**)&bc, g_bias_c);

    cudaFuncSetAttribute(mgemm_k<0,1>, cudaFuncAttributeMaxDynamicSharedMemorySize, MG_SMEM);
    cudaFuncSetAttribute(mgemm_k<1,0>, cudaFuncAttributeMaxDynamicSharedMemorySize, MG_SMEM);
    cudaFuncSetAttribute(mgemm_k<2,1>, cudaFuncAttributeMaxDynamicSharedMemorySize, MG_SMEM);
    cudaFuncSetAttribute(mgemm_k<3,0>, cudaFuncAttributeMaxDynamicSharedMemorySize, MG_SMEM);
    cudaFuncSetAttribute(flash_k, cudaFuncAttributeMaxDynamicSharedMemorySize, FL_SMEM);

    // --- weight prep: transpose + concat + bf16 split ---
    {
        const long long sL = 3145728LL;     // 3072*1024 per layer
        const long long sH = 131072LL;      // 128*1024 per head
        dim3 gq(K_ / 32, M_ / 32, L_ * H_);
        tsplit_k<<<gq, 256>>>(swq, wqkvs_h, wqkvs_l, M_, K_, 3, sL, sH, 0LL);
        tsplit_k<<<gq, 256>>>(swk, wqkvs_h, wqkvs_l, M_, K_, 3, sL, sH, 1048576LL);
        tsplit_k<<<gq, 256>>>(swv, wqkvs_h, wqkvs_l, M_, K_, 3, sL, sH, 2097152LL);
        tsplit_k<<<gq, 256>>>(cwq, wqkvc_h, wqkvc_l, M_, K_, 3, sL, sH, 0LL);
        tsplit_k<<<gq, 256>>>(cwk, wqkvc_h, wqkvc_l, M_, K_, 3, sL, sH, 1048576LL);
        tsplit_k<<<gq, 256>>>(cwv, wqkvc_h, wqkvc_l, M_, K_, 3, sL, sH, 2097152LL);
        dim3 go(M_ / 32, (H_ * V_) / 32, L_);
        tsplit_k<<<go, 256>>>(swo, wos_h, wos_l, H_ * V_, M_, 0, 1048576LL, 0LL, 0LL);
        tsplit_k<<<go, 256>>>(cwo, woc_h, woc_l, H_ * V_, M_, 0, 1048576LL, 0LL, 0LL);
        dim3 g1(F_ / 32, M_ / 32, L_);
        tsplit_k<<<g1, 256>>>(w1, w1h, w1l, M_, F_, 0, 4194304LL, 0LL, 0LL);
        dim3 g2(M_ / 32, F_ / 32, L_);
        tsplit_k<<<g2, 256>>>(w2, w2h, w2l, F_, M_, 0, 4194304LL, 0LL, 0LL);
    }
    split_k<<<B_ * T_ * M_ / 4 / 256, 256>>>(enc_out, eh, el, B_ * T_ * M_ / 4);

    // --- mask bias arrays ---
    bias_build_k<<<B_ * Q_ * T_ / 2 / 256, 256>>>(pmask, qtself, bs);
    bias_build_k<<<B_ * Q_ * T_ / 2 / 256, 256>>>(nullptr, qtcross, bc);

    cudaMemcpyAsync(hb, x, (size_t)BQ_ * M_ * sizeof(float), cudaMemcpyDeviceToDevice);

    const dim3 gQKV(3072 / 128, BQ_ / 128);   // (24,32) fused qkv (self)
    const dim3 gPq (M_ / 128,  BQ_ / 128);    // (8,32)  q-only (cross)
    const dim3 gKV (2048 / 128, BQ_ / 128);   // (16,32) kv (cross)
    const dim3 gP  (M_ / 128,  BQ_ / 128);    // (8,32)  wo / FFN2
    const dim3 gF1 (F_ / 128,  BQ_ / 128);    // (32,32) FFN1
    const dim3 gFL (Q_ / 64, B_ * H_);        // flash
    const long long wS  = 3145728LL;
    const size_t wO  = 1048576;
    const size_t wLF = 4194304;

    for (int l = 0; l < L_; ++l) {
        for (int pass = 0; pass < 2; ++pass) {
            const bool self = (pass == 0);
            const float* lng = self ? ln1g : ln2g;
            const float* lnb = self ? ln1b : ln2b;
            __nv_bfloat16* wcat_h = (self ? wqkvs_h : wqkvc_h) + l * wS;
            __nv_bfloat16* wcat_l = (self ? wqkvs_l : wqkvc_l) + l * wS;
            __nv_bfloat16* wo_h = (self ? wos_h : woc_h) + l * wO;
            __nv_bfloat16* wo_l = (self ? wos_l : woc_l) + l * wO;

            layernorm_split_k<<<BQ_, 256>>>(hb, lng + l * M_, lnb + l * M_, nh, nl);
            if (self) {
                // qkv = n Wqkv^T  (N=3072)
                mgemm_k<0,1><<<gQKV, 256, MG_SMEM>>>(nh, nl, M_, wcat_h, wcat_l, M_,
                                                     nullptr, qkvh, qkvl, 3072,
                                                     nullptr, 0, nullptr, nullptr, M_);
            } else {
                // q = n Wq^T
                mgemm_k<0,1><<<gPq, 256, MG_SMEM>>>(nh, nl, M_, wcat_h, wcat_l, M_,
                                                    nullptr, qkvh, qkvl, 3072,
                                                    nullptr, 0, nullptr, nullptr, M_);
                // kv = enc Wkv^T (N=2048) -> cols 1024..3071
                mgemm_k<0,1><<<gKV, 256, MG_SMEM>>>(eh, el, M_,
                                                    wcat_h + 1048576, wcat_l + 1048576, M_,
                                                    nullptr, qkvh + 1024, qkvl + 1024, 3072,
                                                    nullptr, 0, nullptr, nullptr, M_);
            }
            // fused attention -> pre (split)
            flash_k<<<gFL, 128, FL_SMEM>>>(qkvh, qkvl, self ? bs : bc, ph, pl);
            // h += (pre Wo^T) * (1 - mask)
            mgemm_k<1,0><<<gP, 256, MG_SMEM>>>(ph, pl, M_, wo_h, wo_l, M_,
                                               hb, nullptr, nullptr, M_,
                                               hb, M_, nullptr, pmask, M_);
        }

        // ---- FFN ----
        layernorm_split_k<<<BQ_, 256>>>(hb, ln3g + l * M_, ln3b + l * M_, nh, nl);
        mgemm_k<2,1><<<gF1, 256, MG_SMEM>>>(nh, nl, M_, w1h + l * wLF, w1l + l * wLF, M_,
                                            nullptr, sh, sl, F_,
                                            nullptr, 0, b1 + l * F_, nullptr, M_);
        mgemm_k<3,0><<<gP, 256, MG_SMEM>>>(sh, sl, F_, w2h + l * wLF, w2l + l * wLF, F_,
                                           hb, nullptr, nullptr, M_,
                                           hb, M_, b2 + l * M_, pmask, F_);
    }

    cudaMemcpyAsync(d_out, hb, (size_t)BQ_ * M_ * sizeof(float),
                    cudaMemcpyDeviceToDevice);
}